// round 15
// baseline (speedup 1.0000x reference)
#include <cuda_runtime.h>
#include <cuda_bf16.h>
#include <math.h>
#include <stdint.h>

// ---------------------------------------------------------------------------
// Problem constants
// ---------------------------------------------------------------------------
#define Bc    64
#define Tc    334
#define Fc    1024
#define Uc    1024
#define Ac    64
#define NBc   255
#define NTOK  (Bc * Tc)        // 21376 = 167 * 128
#define TM1   (Tc - 1)         // 333
#define NLOSS (Bc * TM1)       // 21312
#define LAM_C     0.95f
#define ACTENT_C  3e-4f
#define UNIMIX_A  0.00015625f  // 0.01 / 64
#define NCH   32               // K chunks of 32 (K = 1024)

// smem tile: 128 rows x 32 bf16, row stride 40 bf16 (80 B) -> conflict-free ldmatrix
#define TSTRIDE 40
#define TILE_B  (128 * TSTRIDE * 2)   // 10240 bytes
#define STAGE_B (4 * TILE_B)          // 40960 bytes (Ahi,Alo,Bhi,Blo)
#define NSTAGE  2
#define SMEM_B  (NSTAGE * STAGE_B)    // 81920 bytes -> 2 CTAs/SM

// net strides (elements)
#define ASTR ((size_t)NTOK * Uc)
#define WSTR ((size_t)5 * 1024 * 1024)
#define HSTR ((size_t)256 * 1024)
#define LSTR ((size_t)NTOK * NBc)

// ---------------------------------------------------------------------------
// Device scratch — single symbols, net index via stride
// ---------------------------------------------------------------------------
__device__ float g_h0[3 * ASTR];                 // fp32 h (used by s net, z=1)
__device__ __nv_bfloat16 g_hb[3 * ASTR];         // bf16 h (used by v/p nets)
__device__ __nv_bfloat16 g_fhi[ASTR];
__device__ __nv_bfloat16 g_flo[ASTR];
__device__ __nv_bfloat16 g_a_hi[3 * ASTR];
__device__ __nv_bfloat16 g_a_lo[3 * ASTR];
__device__ float g_vslog[2 * LSTR];              // [0]=vlog, [1]=slog
__device__ float g_plog[(size_t)NTOK * Ac];
__device__ float g_smean[NTOK];
__device__ float g_ret[NLOSS];
__device__ float g_wgt[NLOSS];
__device__ float g_scale[4];
__device__ float g_loss[NLOSS];
// split K-major weights (bf16 hi/lo). Head pad rows never written -> stay 0.
__device__ __nv_bfloat16 g_w_hi[3 * WSTR];
__device__ __nv_bfloat16 g_w_lo[3 * WSTR];
__device__ __nv_bfloat16 g_hvs_hi[2 * HSTR];
__device__ __nv_bfloat16 g_hvs_lo[2 * HSTR];
__device__ __nv_bfloat16 g_hp_hi[128 * 1024];
__device__ __nv_bfloat16 g_hp_lo[128 * 1024];

// ---------------------------------------------------------------------------
// helpers
// ---------------------------------------------------------------------------
__device__ __forceinline__ uint32_t smem_u32(const void* p) {
    uint32_t a;
    asm("{ .reg .u64 t; cvta.to.shared.u64 t, %1; cvt.u32.u64 %0, t; }" : "=r"(a) : "l"(p));
    return a;
}
__device__ __forceinline__ void ldm_x4(uint32_t* f, uint32_t addr) {
    asm volatile("ldmatrix.sync.aligned.m8n8.x4.shared.b16 {%0,%1,%2,%3}, [%4];"
                 : "=r"(f[0]), "=r"(f[1]), "=r"(f[2]), "=r"(f[3]) : "r"(addr));
}
__device__ __forceinline__ void mma_bf16(float* c, const uint32_t* a,
                                         uint32_t b0, uint32_t b1) {
    asm volatile(
        "mma.sync.aligned.m16n8k16.row.col.f32.bf16.bf16.f32 "
        "{%0,%1,%2,%3}, {%4,%5,%6,%7}, {%8,%9}, {%0,%1,%2,%3};"
        : "+f"(c[0]), "+f"(c[1]), "+f"(c[2]), "+f"(c[3])
        : "r"(a[0]), "r"(a[1]), "r"(a[2]), "r"(a[3]), "r"(b0), "r"(b1));
}
__device__ __forceinline__ void cp16(uint32_t dst, const void* src) {
    asm volatile("cp.async.ca.shared.global [%0], [%1], 16;" :: "r"(dst), "l"(src));
}
__device__ __forceinline__ void cp_commit() {
    asm volatile("cp.async.commit_group;" ::: "memory");
}
__device__ __forceinline__ void cp_wait1() {
    asm volatile("cp.async.wait_group 1;" ::: "memory");
}
__device__ __forceinline__ void split1(float v, __nv_bfloat16& h, __nv_bfloat16& l) {
    h = __float2bfloat16(v);
    l = __float2bfloat16(v - __bfloat162float(h));
}
#define SEL3(z, a, b, cc) ((z) == 0 ? (a) : (z) == 1 ? (b) : (cc))

// order-preserving float<->uint for radix select
__device__ __forceinline__ uint32_t f2u(float f) {
    uint32_t b = __float_as_uint(f);
    return (b & 0x80000000u) ? ~b : (b | 0x80000000u);
}
__device__ __forceinline__ float u2f(uint32_t u) {
    uint32_t b = (u & 0x80000000u) ? (u & 0x7fffffffu) : ~u;
    return __uint_as_float(b);
}

// ---------------------------------------------------------------------------
// bf16-split tensor-core GEMM. CTA tile 128x128, 4 warps, warp tile 64x64,
// 2 CTAs/SM. Multi-problem via blockIdx.z + strides (z-major keeps L2 reuse).
// loMask bit z: 1 -> full bf16x3 split (3 passes), 0 -> single bf16 pass.
// bfMask bit z: 1 -> write bf16 output to Cb_ (no bias), 0 -> fp32 to C_.
// ---------------------------------------------------------------------------
__global__ __launch_bounds__(128, 2) void tc_gemm(
    const __nv_bfloat16* __restrict__ Ahi_, const __nv_bfloat16* __restrict__ Alo_,
    size_t aStr,
    const __nv_bfloat16* __restrict__ Bhi_, const __nv_bfloat16* __restrict__ Blo_,
    size_t bStr,
    const float* bias0, const float* bias1,
    float* C_, __nv_bfloat16* Cb_, size_t cStr, int Mout,
    int loMask, int bfMask)
{
    extern __shared__ char smem[];
    const uint32_t sb = smem_u32(smem);
    const int z = blockIdx.z;
    const bool p3 = ((loMask >> z) & 1) != 0;
    const bool obf = ((bfMask >> z) & 1) != 0;
    const __nv_bfloat16* __restrict__ Ahi = Ahi_ + (size_t)z * aStr;
    const __nv_bfloat16* __restrict__ Alo = Alo_ + (size_t)z * aStr;
    const __nv_bfloat16* __restrict__ Bhi = Bhi_ + (size_t)z * bStr;
    const __nv_bfloat16* __restrict__ Blo = Blo_ + (size_t)z * bStr;
    const float* bias = (z == 0) ? bias0 : bias1;
    float* __restrict__ C = C_ + (size_t)z * cStr;
    __nv_bfloat16* __restrict__ Cb = Cb_ + (size_t)z * cStr;

    const int tid = threadIdx.x;
    const int lane = tid & 31;
    const int warp = tid >> 5;          // 0..3
    const int brow = blockIdx.x * 128;
    const int bcol = blockIdx.y * 128;

    const int m0w = (warp >> 1) * 64;
    const int n0w = (warp & 1) * 64;
    const int lrow = lane & 15;
    const int lcol8 = (lane >> 4) << 3;

    float c[4][8][4];
    #pragma unroll
    for (int i = 0; i < 4; i++)
        #pragma unroll
        for (int j = 0; j < 8; j++)
            #pragma unroll
            for (int q = 0; q < 4; q++) c[i][j][q] = 0.f;

    // cp.async: 2048 x 16B atoms per stage over 128 threads -> 16 per thread
    auto issue = [&](int stage, int ch) {
        const int k0 = ch * 32;
        #pragma unroll
        for (int j = 0; j < 16; j++) {
            int gid = tid + 128 * j;
            int tl = gid >> 9;           // 0=Ahi 1=Alo 2=Bhi 3=Blo
            int t = gid & 511;
            int r = t >> 2, a = t & 3;
            const __nv_bfloat16* base =
                (tl == 0) ? Ahi : (tl == 1) ? Alo : (tl == 2) ? Bhi : Blo;
            int grow = ((tl < 2) ? brow : bcol) + r;
            const __nv_bfloat16* src = base + (size_t)grow * 1024 + k0 + a * 8;
            uint32_t dst = sb + (uint32_t)stage * STAGE_B + (uint32_t)tl * TILE_B
                         + (uint32_t)(r * 80 + a * 16);
            if (p3 || tl == 0 || tl == 2) cp16(dst, src);
        }
        cp_commit();
    };

    issue(0, 0);
    issue(1, 1);

    for (int ch = 0; ch < NCH; ch++) {
        cp_wait1();
        __syncthreads();

        const uint32_t base = sb + (uint32_t)(ch & 1) * STAGE_B;
        #pragma unroll
        for (int ss = 0; ss < 2; ss++) {
            const int kk = ss * 16;
            const uint32_t aoff = (uint32_t)((m0w + lrow) * TSTRIDE + kk + lcol8) * 2;
            const uint32_t boff = (uint32_t)((n0w + lrow) * TSTRIDE + kk + lcol8) * 2;
            const uint32_t fstep = (uint32_t)(16 * TSTRIDE) * 2;

            uint32_t aHi[4][4], bH[4][4];
            #pragma unroll
            for (int i = 0; i < 4; i++)
                ldm_x4(aHi[i], base + aoff + (uint32_t)i * fstep);
            #pragma unroll
            for (int g = 0; g < 4; g++)
                ldm_x4(bH[g], base + 2 * TILE_B + boff + (uint32_t)g * fstep);

            // pass 1: Ahi x Bhi (32 independent MMAs)
            #pragma unroll
            for (int g = 0; g < 4; g++)
                #pragma unroll
                for (int i = 0; i < 4; i++) {
                    mma_bf16(c[i][2 * g],     aHi[i], bH[g][0], bH[g][2]);
                    mma_bf16(c[i][2 * g + 1], aHi[i], bH[g][1], bH[g][3]);
                }

            if (p3) {
                // pass 2: Alo x Bhi, aLo loaded one-ahead (transient)
                uint32_t aL0[4], aL1[4];
                ldm_x4(aL0, base + TILE_B + aoff);
                #pragma unroll
                for (int i = 0; i < 4; i++) {
                    uint32_t* cur = (i & 1) ? aL1 : aL0;
                    uint32_t* nxt = (i & 1) ? aL0 : aL1;
                    if (i < 3)
                        ldm_x4(nxt, base + TILE_B + aoff + (uint32_t)(i + 1) * fstep);
                    #pragma unroll
                    for (int g = 0; g < 4; g++) {
                        mma_bf16(c[i][2 * g],     cur, bH[g][0], bH[g][2]);
                        mma_bf16(c[i][2 * g + 1], cur, bH[g][1], bH[g][3]);
                    }
                }
                // pass 3: Ahi x Blo, bL loaded one-ahead (transient)
                uint32_t bL0[4], bL1[4];
                ldm_x4(bL0, base + 3 * TILE_B + boff);
                #pragma unroll
                for (int g = 0; g < 4; g++) {
                    uint32_t* cur = (g & 1) ? bL1 : bL0;
                    uint32_t* nxt = (g & 1) ? bL0 : bL1;
                    if (g < 3)
                        ldm_x4(nxt, base + 3 * TILE_B + boff + (uint32_t)(g + 1) * fstep);
                    #pragma unroll
                    for (int i = 0; i < 4; i++) {
                        mma_bf16(c[i][2 * g],     aHi[i], cur[0], cur[2]);
                        mma_bf16(c[i][2 * g + 1], aHi[i], cur[1], cur[3]);
                    }
                }
            }
        }
        __syncthreads();
        if (ch + NSTAGE < NCH) issue(ch & 1, ch + NSTAGE);
        else cp_commit();
    }

    // epilogue: warp tile 64x64
    const int r = lane >> 2;
    const int cc = 2 * (lane & 3);
    if (obf) {
        // bf16 output (layer h for v/p nets; bias always null here, Mout mult of 2)
        #pragma unroll
        for (int i = 0; i < 4; i++) {
            int rowb = brow + m0w + i * 16;
            #pragma unroll
            for (int j = 0; j < 8; j++) {
                int col = bcol + n0w + j * 8 + cc;
                __nv_bfloat162 v0(__float2bfloat16(c[i][j][0]),
                                  __float2bfloat16(c[i][j][1]));
                __nv_bfloat162 v1(__float2bfloat16(c[i][j][2]),
                                  __float2bfloat16(c[i][j][3]));
                *(__nv_bfloat162*)(Cb + (size_t)(rowb + r) * Mout + col) = v0;
                *(__nv_bfloat162*)(Cb + (size_t)(rowb + r + 8) * Mout + col) = v1;
            }
        }
    } else {
        #pragma unroll
        for (int i = 0; i < 4; i++) {
            int rowb = brow + m0w + i * 16;
            #pragma unroll
            for (int j = 0; j < 8; j++) {
                int col = bcol + n0w + j * 8 + cc;
                float b0 = 0.f, b1 = 0.f;
                if (bias) {
                    if (col < Mout) b0 = bias[col];
                    if (col + 1 < Mout) b1 = bias[col + 1];
                }
                float* p0 = C + (size_t)(rowb + r) * Mout + col;
                float* p1 = C + (size_t)(rowb + r + 8) * Mout + col;
                if (col + 1 < Mout) {
                    p0[0] = c[i][j][0] + b0; p0[1] = c[i][j][1] + b1;
                    p1[0] = c[i][j][2] + b0; p1[1] = c[i][j][3] + b1;
                } else if (col < Mout) {
                    p0[0] = c[i][j][0] + b0;
                    p1[0] = c[i][j][2] + b0;
                }
            }
        }
    }
}

// ---------------------------------------------------------------------------
// all 15 square weight transpose+splits in one launch (z = net*5 + layer)
// lo written only for net 1 (slow) — v/p lo is never read
// ---------------------------------------------------------------------------
__global__ __launch_bounds__(256) void split_wt15_kernel(
    const float* Win0, const float* Win1, const float* Win2,
    const float* Whid0, const float* Whid1, const float* Whid2,
    __nv_bfloat16* Whi, __nv_bfloat16* Wlo)
{
    __shared__ float t[32][33];
    int z = blockIdx.z;
    int net = z / 5, layer = z % 5;
    const float* Win  = SEL3(net, Win0, Win1, Win2);
    const float* Whid = SEL3(net, Whid0, Whid1, Whid2);
    const float* W = (layer == 0) ? Win : (Whid + (size_t)(layer - 1) * Uc * Uc);
    __nv_bfloat16* dhi = Whi + (size_t)net * WSTR + (size_t)layer * Uc * Uc;
    __nv_bfloat16* dlo = Wlo + (size_t)net * WSTR + (size_t)layer * Uc * Uc;
    int k0 = blockIdx.x * 32, m0 = blockIdx.y * 32;
    int x = threadIdx.x, y = threadIdx.y;   // 32 x 8
    #pragma unroll
    for (int j = 0; j < 32; j += 8)
        t[y + j][x] = W[(size_t)(k0 + y + j) * Uc + m0 + x];
    __syncthreads();
    #pragma unroll
    for (int j = 0; j < 32; j += 8) {
        int m = m0 + y + j;
        float v = t[x][y + j];
        __nv_bfloat16 h, l;
        split1(v, h, l);
        dhi[(size_t)m * 1024 + k0 + x] = h;
        if (net == 1) dlo[(size_t)m * 1024 + k0 + x] = l;
    }
}

// head transpose + split: W[1024, M] -> [M,1024]
__global__ __launch_bounds__(256) void split_wt_kernel(
    const float* __restrict__ W, __nv_bfloat16* __restrict__ Whi,
    __nv_bfloat16* __restrict__ Wlo, int M)
{
    __shared__ float t[32][33];
    int k0 = blockIdx.x * 32, m0 = blockIdx.y * 32;
    int x = threadIdx.x, y = threadIdx.y;
    #pragma unroll
    for (int j = 0; j < 32; j += 8) {
        int m = m0 + x;
        if (m < M) t[y + j][x] = W[(size_t)(k0 + y + j) * M + m];
    }
    __syncthreads();
    #pragma unroll
    for (int j = 0; j < 32; j += 8) {
        int m = m0 + y + j;
        if (m < M) {
            float v = t[x][y + j];
            __nv_bfloat16 h, l;
            split1(v, h, l);
            Whi[(size_t)m * 1024 + k0 + x] = h;
            Wlo[(size_t)m * 1024 + k0 + x] = l;
        }
    }
}

// ---------------------------------------------------------------------------
// feat split
// ---------------------------------------------------------------------------
__global__ __launch_bounds__(256) void split_act_kernel(
    const float* __restrict__ X, __nv_bfloat16* __restrict__ Hi,
    __nv_bfloat16* __restrict__ Lo)
{
    size_t i = (size_t)blockIdx.x * 256 + threadIdx.x;
    float4 v = ((const float4*)X)[i];
    __nv_bfloat16 hx, hy, hz, hw, lx, ly, lz, lw;
    split1(v.x, hx, lx); split1(v.y, hy, ly);
    split1(v.z, hz, lz); split1(v.w, hw, lw);
    __nv_bfloat162 h0(hx, hy), h1(hz, hw), l0(lx, ly), l1(lz, lw);
    uint2 hp, lp;
    hp.x = *(uint32_t*)&h0; hp.y = *(uint32_t*)&h1;
    lp.x = *(uint32_t*)&l0; lp.y = *(uint32_t*)&l1;
    ((uint2*)Hi)[i] = hp;
    ((uint2*)Lo)[i] = lp;
}

// ---------------------------------------------------------------------------
// fused rmsnorm + silu + split for 3 nets; net 1 reads fp32 Xf, nets 0/2 read
// bf16 Xb; Lo written only for net 1 (slow)
// ---------------------------------------------------------------------------
__device__ __forceinline__ float silu_f(float z) { return z / (1.f + expf(-z)); }

__global__ __launch_bounds__(256) void rms3_kernel(
    const float* __restrict__ Xf, const __nv_bfloat16* __restrict__ Xb,
    const float* g0, const float* g1, const float* g2,
    __nv_bfloat16* __restrict__ Hi, __nv_bfloat16* __restrict__ Lo)
{
    int net = blockIdx.y;
    int row = blockIdx.x;
    int t = threadIdx.x;
    const float* g = SEL3(net, g0, g1, g2);
    size_t off = (size_t)net * ASTR + (size_t)row * Uc;

    float4 xv;
    if (net == 1) {
        xv = ((const float4*)(Xf + off))[t];
    } else {
        uint2 u = ((const uint2*)(Xb + off))[t];
        __nv_bfloat162 b0 = *(__nv_bfloat162*)&u.x;
        __nv_bfloat162 b1 = *(__nv_bfloat162*)&u.y;
        xv.x = __bfloat162float(b0.x);
        xv.y = __bfloat162float(b0.y);
        xv.z = __bfloat162float(b1.x);
        xv.w = __bfloat162float(b1.y);
    }
    float ss = xv.x * xv.x + xv.y * xv.y + xv.z * xv.z + xv.w * xv.w;
    #pragma unroll
    for (int o = 16; o; o >>= 1) ss += __shfl_xor_sync(0xffffffffu, ss, o);
    __shared__ float sh[8];
    if ((t & 31) == 0) sh[t >> 5] = ss;
    __syncthreads();
    if (t < 32) {
        float v = (t < 8) ? sh[t] : 0.f;
        #pragma unroll
        for (int o = 4; o; o >>= 1) v += __shfl_xor_sync(0xffffffffu, v, o);
        if (t == 0) sh[0] = v;
    }
    __syncthreads();
    float r = rsqrtf(sh[0] * (1.0f / (float)Uc) + 1e-6f);
    float4 gv = ((const float4*)g)[t];
    float4 o;
    o.x = silu_f(xv.x * r * gv.x);
    o.y = silu_f(xv.y * r * gv.y);
    o.z = silu_f(xv.z * r * gv.z);
    o.w = silu_f(xv.w * r * gv.w);
    __nv_bfloat16 hx, hy, hz, hw, lx, ly, lz, lw;
    split1(o.x, hx, lx); split1(o.y, hy, ly);
    split1(o.z, hz, lz); split1(o.w, hw, lw);
    __nv_bfloat162 h0(hx, hy), h1(hz, hw), l0(lx, ly), l1(lz, lw);
    uint2 hp, lp;
    hp.x = *(uint32_t*)&h0; hp.y = *(uint32_t*)&h1;
    lp.x = *(uint32_t*)&l0; lp.y = *(uint32_t*)&l1;
    ((uint2*)(Hi + off))[t] = hp;
    if (net == 1) ((uint2*)(Lo + off))[t] = lp;
}

// ---------------------------------------------------------------------------
// symexp bins
// ---------------------------------------------------------------------------
__device__ __forceinline__ float bin_val(int i) {
    float u = -20.0f + (40.0f / 254.0f) * (float)i;
    return copysignf(expm1f(fabsf(u)), u);
}

// ---------------------------------------------------------------------------
// slow_mean
// ---------------------------------------------------------------------------
__global__ __launch_bounds__(256) void slowmean_kernel(
    const float* __restrict__ slog, float* __restrict__ smean)
{
    __shared__ float sred[8];
    __shared__ double dden[8], dnum[8];
    int row = blockIdx.x, tid = threadIdx.x;
    float lg = -3.4e38f, bn = 0.f;
    if (tid < NBc) {
        lg = slog[(size_t)row * NBc + tid];
        bn = bin_val(tid);
    }
    float m = lg;
    #pragma unroll
    for (int o = 16; o; o >>= 1) m = fmaxf(m, __shfl_xor_sync(0xffffffffu, m, o));
    if ((tid & 31) == 0) sred[tid >> 5] = m;
    __syncthreads();
    if (tid < 32) {
        float v = (tid < 8) ? sred[tid] : -3.4e38f;
        #pragma unroll
        for (int o = 4; o; o >>= 1) v = fmaxf(v, __shfl_xor_sync(0xffffffffu, v, o));
        if (tid == 0) sred[0] = v;
    }
    __syncthreads();
    float M = sred[0];
    float e = (tid < NBc) ? expf(lg - M) : 0.f;
    double den = (double)e;
    double num = (double)e * (double)bn;
    #pragma unroll
    for (int o = 16; o; o >>= 1) {
        den += __shfl_xor_sync(0xffffffffu, den, o);
        num += __shfl_xor_sync(0xffffffffu, num, o);
    }
    if ((tid & 31) == 0) { dden[tid >> 5] = den; dnum[tid >> 5] = num; }
    __syncthreads();
    if (tid == 0) {
        double D = 0, Nn = 0;
        #pragma unroll
        for (int i = 0; i < 8; i++) { D += dden[i]; Nn += dnum[i]; }
        smean[row] = (float)(Nn / D);
    }
}

// ---------------------------------------------------------------------------
// lambda-return scan
// ---------------------------------------------------------------------------
__global__ void lamret_kernel(
    const float* __restrict__ reward, const float* __restrict__ cont,
    const float* __restrict__ smean, float* __restrict__ ret, float* __restrict__ wgt)
{
    int b = threadIdx.x;
    if (b >= Bc) return;
    float acc = 1.f;
    for (int t = 0; t < TM1; t++) {
        acc *= cont[b * Tc + t];
        wgt[b * TM1 + t] = acc;
    }
    float r = smean[b * Tc + (Tc - 1)];
    for (int t = TM1 - 1; t >= 0; t--) {
        float live = cont[b * Tc + t + 1];
        float interm = reward[b * Tc + t + 1] + (1.f - LAM_C) * live * smean[b * Tc + t + 1];
        r = interm + live * LAM_C * r;
        ret[b * TM1 + t] = r;
    }
}

// ---------------------------------------------------------------------------
// exact 5th/95th percentile via 3-round histogram radix select (1 block)
// ---------------------------------------------------------------------------
__global__ __launch_bounds__(1024) void percentile_kernel(
    const float* __restrict__ ret, float* __restrict__ scale)
{
    __shared__ uint32_t hist[4][2048];
    __shared__ uint32_t pref[4];
    __shared__ uint32_t rem[4];
    __shared__ uint32_t vals[4];
    const int tid = threadIdx.x;
    const uint32_t RK0 = 1065u, RK1 = 1066u, RK2 = 20245u, RK3 = 20246u;

    for (int i = tid; i < 2048; i += 1024) hist[0][i] = 0;
    __syncthreads();
    for (int i = tid; i < NLOSS; i += 1024)
        atomicAdd(&hist[0][f2u(ret[i]) >> 21], 1u);
    __syncthreads();
    if (tid == 0) {
        uint32_t RK[4] = {RK0, RK1, RK2, RK3};
        for (int t = 0; t < 4; t++) {
            uint32_t cum = 0, r = RK[t];
            for (uint32_t b = 0; b < 2048; b++) {
                uint32_t c = hist[0][b];
                if (cum + c > r) { pref[t] = b << 21; rem[t] = r - cum; break; }
                cum += c;
            }
        }
    }
    __syncthreads();
    for (int i = tid; i < 4 * 2048; i += 1024) (&hist[0][0])[i] = 0;
    __syncthreads();
    for (int i = tid; i < NLOSS; i += 1024) {
        uint32_t u = f2u(ret[i]);
        uint32_t top = u & 0xFFE00000u;
        uint32_t mid = (u >> 10) & 2047u;
        #pragma unroll
        for (int t = 0; t < 4; t++)
            if (top == pref[t]) atomicAdd(&hist[t][mid], 1u);
    }
    __syncthreads();
    if (tid == 0) {
        for (int t = 0; t < 4; t++) {
            uint32_t cum = 0, r = rem[t];
            for (uint32_t b = 0; b < 2048; b++) {
                uint32_t c = hist[t][b];
                if (cum + c > r) { pref[t] |= b << 10; rem[t] = r - cum; break; }
                cum += c;
            }
        }
    }
    __syncthreads();
    for (int i = tid; i < 4 * 2048; i += 1024) (&hist[0][0])[i] = 0;
    __syncthreads();
    for (int i = tid; i < NLOSS; i += 1024) {
        uint32_t u = f2u(ret[i]);
        uint32_t top = u & 0xFFFFFC00u;
        uint32_t lo10 = u & 1023u;
        #pragma unroll
        for (int t = 0; t < 4; t++)
            if (top == pref[t]) atomicAdd(&hist[t][lo10], 1u);
    }
    __syncthreads();
    if (tid == 0) {
        for (int t = 0; t < 4; t++) {
            uint32_t cum = 0, r = rem[t];
            for (uint32_t b = 0; b < 1024; b++) {
                uint32_t c = hist[t][b];
                if (cum + c > r) { vals[t] = pref[t] | b; break; }
                cum += c;
            }
        }
        float v5a = u2f(vals[0]), v5b = u2f(vals[1]);
        float v95a = u2f(vals[2]), v95b = u2f(vals[3]);
        double p5 = 0.05 * (double)(NLOSS - 1);
        double p95 = 0.95 * (double)(NLOSS - 1);
        int i5 = (int)p5, i95 = (int)p95;
        float f5 = (float)(p5 - i5), f95 = (float)(p95 - i95);
        float lo = v5a + f5 * (v5b - v5a);
        float hi = v95a + f95 * (v95b - v95a);
        scale[0] = lo;
        scale[1] = hi;
        scale[2] = fmaxf(hi - lo, 1.0f);
    }
}

// ---------------------------------------------------------------------------
// per-token loss
// ---------------------------------------------------------------------------
__device__ __forceinline__ float twohot_nll(const float* svl, const float* sbins,
                                            float logZ, float y)
{
    y = fminf(fmaxf(y, sbins[0]), sbins[NBc - 1]);
    int lo = 0, hi = NBc - 1;
    while (hi > lo) {
        int mid = (lo + hi) >> 1;
        if (sbins[mid] >= y) hi = mid; else lo = mid + 1;
    }
    int k = hi - 1;
    if (k < 0) k = 0;
    if (k > NBc - 2) k = NBc - 2;
    float bl = sbins[k], bh = sbins[k + 1];
    float w = (y - bl) / (bh - bl);
    w = fminf(fmaxf(w, 0.f), 1.f);
    float l0 = svl[k] - logZ, l1 = svl[k + 1] - logZ;
    return -((1.f - w) * l0 + w * l1);
}

__global__ __launch_bounds__(256) void loss_kernel(
    const float* __restrict__ vlog, const float* __restrict__ plog,
    const float* __restrict__ smean, const float* __restrict__ ret,
    const float* __restrict__ wgt, const int* __restrict__ act,
    const float* __restrict__ scale, float* __restrict__ loss)
{
    __shared__ float sbins[NBc];
    __shared__ float svl[NBc];
    __shared__ float sred[8];
    __shared__ float sres[4];

    int i = blockIdx.x;
    int b = i / TM1, t = i - b * TM1;
    int row = b * Tc + t;
    int tid = threadIdx.x;

    if (tid < NBc) {
        sbins[tid] = bin_val(tid);
        svl[tid] = vlog[(size_t)row * NBc + tid];
    }
    __syncthreads();

    float v = (tid < NBc) ? svl[tid] : -3.4e38f;
    #pragma unroll
    for (int o = 16; o; o >>= 1) v = fmaxf(v, __shfl_xor_sync(0xffffffffu, v, o));
    if ((tid & 31) == 0) sred[tid >> 5] = v;
    __syncthreads();
    if (tid < 32) {
        float m = (tid < 8) ? sred[tid] : -3.4e38f;
        #pragma unroll
        for (int o = 4; o; o >>= 1) m = fmaxf(m, __shfl_xor_sync(0xffffffffu, m, o));
        if (tid == 0) sres[0] = m;
    }
    __syncthreads();
    float M = sres[0];
    float e = (tid < NBc) ? expf(svl[tid] - M) : 0.f;
    #pragma unroll
    for (int o = 16; o; o >>= 1) e += __shfl_xor_sync(0xffffffffu, e, o);
    if ((tid & 31) == 0) sred[tid >> 5] = e;
    __syncthreads();
    if (tid < 32) {
        float s = (tid < 8) ? sred[tid] : 0.f;
        #pragma unroll
        for (int o = 4; o; o >>= 1) s += __shfl_xor_sync(0xffffffffu, s, o);
        if (tid == 0) sres[0] = M + logf(s);
    }
    __syncthreads();
    float logZ = sres[0];

    if (tid < 32) {
        float p0 = plog[(size_t)row * Ac + tid];
        float p1 = plog[(size_t)row * Ac + tid + 32];
        float m = fmaxf(p0, p1);
        #pragma unroll
        for (int o = 16; o; o >>= 1) m = fmaxf(m, __shfl_xor_sync(0xffffffffu, m, o));
        float e0 = expf(p0 - m), e1 = expf(p1 - m);
        float s = e0 + e1;
        #pragma unroll
        for (int o = 16; o; o >>= 1) s += __shfl_xor_sync(0xffffffffu, s, o);
        float inv = 1.0f / s;
        float pr0 = 0.99f * e0 * inv + UNIMIX_A;
        float pr1 = 0.99f * e1 * inv + UNIMIX_A;
        float lp0 = logf(pr0), lp1 = logf(pr1);
        float entp = -(pr0 * lp0 + pr1 * lp1);
        #pragma unroll
        for (int o = 16; o; o >>= 1) entp += __shfl_xor_sync(0xffffffffu, entp, o);
        int a = act[row];
        float lpi = (a == tid) ? lp0 : ((a == tid + 32) ? lp1 : 0.f);
        #pragma unroll
        for (int o = 16; o; o >>= 1) lpi += __shfl_xor_sync(0xffffffffu, lpi, o);
        if (tid == 0) { sres[1] = entp; sres[2] = lpi; }
    }
    __syncthreads();

    if (tid == 0) {
        float reti = ret[i];
        float sm = smean[row];
        float rscale = scale[2];
        float adv = (reti - sm) / rscale;
        float wt = wgt[i];
        float pl = wt * -(sres[2] * adv + ACTENT_C * sres[1]);
        float vl = twohot_nll(svl, sbins, logZ, reti) + twohot_nll(svl, sbins, logZ, sm);
        loss[i] = pl + wt * vl;
    }
}

// ---------------------------------------------------------------------------
// final reduction
// ---------------------------------------------------------------------------
__global__ __launch_bounds__(1024) void reduce_kernel(
    const float* __restrict__ loss, float* __restrict__ out)
{
    __shared__ double sd[32];
    double s = 0.0;
    for (int i = threadIdx.x; i < NLOSS; i += 1024) s += (double)loss[i];
    #pragma unroll
    for (int o = 16; o; o >>= 1) s += __shfl_xor_sync(0xffffffffu, s, o);
    if ((threadIdx.x & 31) == 0) sd[threadIdx.x >> 5] = s;
    __syncthreads();
    if (threadIdx.x == 0) {
        double tot = 0.0;
        #pragma unroll
        for (int w = 0; w < 32; w++) tot += sd[w];
        out[0] = (float)(tot / (double)NLOSS);
    }
}

// ---------------------------------------------------------------------------
// host
// ---------------------------------------------------------------------------
extern "C" void kernel_launch(void* const* d_in, const int* in_sizes, int n_in,
                              void* d_out, int out_size)
{
    const float* feat   = (const float*)d_in[0];
    const float* reward = (const float*)d_in[1];
    const float* cont   = (const float*)d_in[2];
    const int*   act    = (const int*)  d_in[3];
    const float* pW_in  = (const float*)d_in[4];
    const float* pW_hid = (const float*)d_in[5];
    const float* p_gn   = (const float*)d_in[6];
    const float* pHw    = (const float*)d_in[7];
    const float* pHb    = (const float*)d_in[8];
    const float* vW_in  = (const float*)d_in[9];
    const float* vW_hid = (const float*)d_in[10];
    const float* v_gn   = (const float*)d_in[11];
    const float* vHw    = (const float*)d_in[12];
    const float* vHb    = (const float*)d_in[13];
    const float* sW_in  = (const float*)d_in[14];
    const float* sW_hid = (const float*)d_in[15];
    const float* s_gn   = (const float*)d_in[16];
    const float* sHw    = (const float*)d_in[17];
    const float* sHb    = (const float*)d_in[18];

    float *h0, *vslog, *plg, *smean, *ret, *wgt, *scale, *loss;
    __nv_bfloat16 *hb, *fhi, *flo, *a_hi, *a_lo, *w_hi, *w_lo;
    __nv_bfloat16 *hvs_hi, *hvs_lo, *hp_hi, *hp_lo;
    cudaGetSymbolAddress((void**)&h0, g_h0);
    cudaGetSymbolAddress((void**)&hb, g_hb);
    cudaGetSymbolAddress((void**)&fhi, g_fhi);
    cudaGetSymbolAddress((void**)&flo, g_flo);
    cudaGetSymbolAddress((void**)&a_hi, g_a_hi);
    cudaGetSymbolAddress((void**)&a_lo, g_a_lo);
    cudaGetSymbolAddress((void**)&vslog, g_vslog);
    cudaGetSymbolAddress((void**)&plg, g_plog);
    cudaGetSymbolAddress((void**)&smean, g_smean);
    cudaGetSymbolAddress((void**)&ret, g_ret);
    cudaGetSymbolAddress((void**)&wgt, g_wgt);
    cudaGetSymbolAddress((void**)&scale, g_scale);
    cudaGetSymbolAddress((void**)&loss, g_loss);
    cudaGetSymbolAddress((void**)&w_hi, g_w_hi);
    cudaGetSymbolAddress((void**)&w_lo, g_w_lo);
    cudaGetSymbolAddress((void**)&hvs_hi, g_hvs_hi);
    cudaGetSymbolAddress((void**)&hvs_lo, g_hvs_lo);
    cudaGetSymbolAddress((void**)&hp_hi, g_hp_hi);
    cudaGetSymbolAddress((void**)&hp_lo, g_hp_lo);

    float* vlog = vslog;
    float* slog = vslog + LSTR;

    cudaFuncSetAttribute(tc_gemm, cudaFuncAttributeMaxDynamicSharedMemorySize, SMEM_B);

    dim3 tb(32, 8);
    split_wt15_kernel<<<dim3(32, 32, 15), tb>>>(
        vW_in, sW_in, pW_in, vW_hid, sW_hid, pW_hid, w_hi, w_lo);
    split_act_kernel<<<NTOK, 256>>>(feat, fhi, flo);
    split_wt_kernel<<<dim3(32, 2), tb>>>(pHw, hp_hi, hp_lo, Ac);

    // 5 fused layer GEMMs (net: 0=v x1/bf16out, 1=s x3/fp32out, 2=p x1/bf16out)
    for (int l = 0; l < 5; l++) {
        const __nv_bfloat16* Ah = (l == 0) ? fhi : a_hi;
        const __nv_bfloat16* Al = (l == 0) ? flo : a_lo;
        size_t aStr = (l == 0) ? 0 : ASTR;
        tc_gemm<<<dim3(NTOK / 128, 8, 3), 128, SMEM_B>>>(
            Ah, Al, aStr,
            w_hi + (size_t)l * Uc * Uc, w_lo + (size_t)l * Uc * Uc, WSTR,
            nullptr, nullptr, h0, hb, ASTR, Uc,
            /*loMask=*/0b010, /*bfMask=*/0b101);
        rms3_kernel<<<dim3(NTOK, 3), 256>>>(
            h0, hb, v_gn + (size_t)l * Uc, s_gn + (size_t)l * Uc, p_gn + (size_t)l * Uc,
            a_hi, a_lo);
    }

    // head weight splits (needed only now)
    split_wt_kernel<<<dim3(32, 8), tb>>>(vHw, hvs_hi, hvs_lo, NBc);
    split_wt_kernel<<<dim3(32, 8), tb>>>(sHw, hvs_hi + HSTR, hvs_lo + HSTR, NBc);

    // heads: v+s fused (net 0 = v x1, net 1 = s x3), p separate (x1); fp32 out
    tc_gemm<<<dim3(NTOK / 128, 2, 2), 128, SMEM_B>>>(
        a_hi, a_lo, ASTR, hvs_hi, hvs_lo, HSTR,
        vHb, sHb, vslog, hb, LSTR, NBc, /*loMask=*/0b10, /*bfMask=*/0);
    tc_gemm<<<dim3(NTOK / 128, 1, 1), 128, SMEM_B>>>(
        a_hi + 2 * ASTR, a_lo + 2 * ASTR, 0, hp_hi, hp_lo, 0,
        pHb, nullptr, plg, hb, 0, Ac, /*loMask=*/0, /*bfMask=*/0);

    slowmean_kernel<<<NTOK, 256>>>(slog, smean);
    lamret_kernel<<<1, 64>>>(reward, cont, smean, ret, wgt);
    percentile_kernel<<<1, 1024>>>(ret, scale);
    loss_kernel<<<NLOSS, 256>>>(vlog, plg, smean, ret, wgt, act, scale, loss);
    reduce_kernel<<<1, 1024>>>(loss, (float*)d_out);
}

// round 16
// speedup vs baseline: 1.5069x; 1.5069x over previous
#include <cuda_runtime.h>
#include <cuda_bf16.h>
#include <math.h>
#include <stdint.h>

// ---------------------------------------------------------------------------
// Problem constants
// ---------------------------------------------------------------------------
#define Bc    64
#define Tc    334
#define Fc    1024
#define Uc    1024
#define Ac    64
#define NBc   255
#define NTOK  (Bc * Tc)        // 21376 = 167 * 128
#define TM1   (Tc - 1)         // 333
#define NLOSS (Bc * TM1)       // 21312
#define LAM_C     0.95f
#define ACTENT_C  3e-4f
#define UNIMIX_A  0.00015625f  // 0.01 / 64
#define NCH   32               // K chunks of 32 (K = 1024)

// smem tile: 128 rows x 32 bf16, row stride 40 bf16 (80 B) -> conflict-free ldmatrix
#define TSTRIDE 40
#define TILE_B  (128 * TSTRIDE * 2)   // 10240 bytes
#define STAGE_B (4 * TILE_B)          // 40960 bytes (Ahi,Alo,Bhi,Blo)
#define NSTAGE  2
#define SMEM_B  (NSTAGE * STAGE_B)    // 81920 bytes -> 2 CTAs/SM

// net strides (elements)
#define ASTR ((size_t)NTOK * Uc)
#define WSTR ((size_t)5 * 1024 * 1024)
#define HSTR ((size_t)256 * 1024)
#define LSTR ((size_t)NTOK * NBc)

// ---------------------------------------------------------------------------
// Device scratch — single symbols, net index via stride
// ---------------------------------------------------------------------------
__device__ float g_h0[3 * ASTR];
__device__ __nv_bfloat16 g_fhi[ASTR];
__device__ __nv_bfloat16 g_flo[ASTR];
__device__ __nv_bfloat16 g_a_hi[3 * ASTR];
__device__ __nv_bfloat16 g_a_lo[3 * ASTR];
__device__ float g_vslog[2 * LSTR];          // [0]=vlog, [1]=slog
__device__ float g_plog[(size_t)NTOK * Ac];
__device__ float g_smean[NTOK];
__device__ float g_ret[NLOSS];
__device__ float g_wgt[NLOSS];
__device__ float g_scale[4];
__device__ float g_loss[NLOSS];
// split K-major weights (bf16 hi/lo). Head pad rows never written -> stay 0.
__device__ __nv_bfloat16 g_w_hi[3 * WSTR];
__device__ __nv_bfloat16 g_w_lo[3 * WSTR];
__device__ __nv_bfloat16 g_hvs_hi[2 * HSTR];
__device__ __nv_bfloat16 g_hvs_lo[2 * HSTR];
__device__ __nv_bfloat16 g_hp_hi[128 * 1024];
__device__ __nv_bfloat16 g_hp_lo[128 * 1024];

// ---------------------------------------------------------------------------
// helpers
// ---------------------------------------------------------------------------
__device__ __forceinline__ uint32_t smem_u32(const void* p) {
    uint32_t a;
    asm("{ .reg .u64 t; cvta.to.shared.u64 t, %1; cvt.u32.u64 %0, t; }" : "=r"(a) : "l"(p));
    return a;
}
__device__ __forceinline__ void ldm_x4(uint32_t* f, uint32_t addr) {
    asm volatile("ldmatrix.sync.aligned.m8n8.x4.shared.b16 {%0,%1,%2,%3}, [%4];"
                 : "=r"(f[0]), "=r"(f[1]), "=r"(f[2]), "=r"(f[3]) : "r"(addr));
}
__device__ __forceinline__ void mma_bf16(float* c, const uint32_t* a,
                                         uint32_t b0, uint32_t b1) {
    asm volatile(
        "mma.sync.aligned.m16n8k16.row.col.f32.bf16.bf16.f32 "
        "{%0,%1,%2,%3}, {%4,%5,%6,%7}, {%8,%9}, {%0,%1,%2,%3};"
        : "+f"(c[0]), "+f"(c[1]), "+f"(c[2]), "+f"(c[3])
        : "r"(a[0]), "r"(a[1]), "r"(a[2]), "r"(a[3]), "r"(b0), "r"(b1));
}
__device__ __forceinline__ void cp16(uint32_t dst, const void* src) {
    asm volatile("cp.async.ca.shared.global [%0], [%1], 16;" :: "r"(dst), "l"(src));
}
__device__ __forceinline__ void cp_commit() {
    asm volatile("cp.async.commit_group;" ::: "memory");
}
__device__ __forceinline__ void cp_wait1() {
    asm volatile("cp.async.wait_group 1;" ::: "memory");
}
__device__ __forceinline__ void split1(float v, __nv_bfloat16& h, __nv_bfloat16& l) {
    h = __float2bfloat16(v);
    l = __float2bfloat16(v - __bfloat162float(h));
}
#define SEL3(z, a, b, cc) ((z) == 0 ? (a) : (z) == 1 ? (b) : (cc))

// order-preserving float<->uint for radix select
__device__ __forceinline__ uint32_t f2u(float f) {
    uint32_t b = __float_as_uint(f);
    return (b & 0x80000000u) ? ~b : (b | 0x80000000u);
}
__device__ __forceinline__ float u2f(uint32_t u) {
    uint32_t b = (u & 0x80000000u) ? (u & 0x7fffffffu) : ~u;
    return __uint_as_float(b);
}

// ---------------------------------------------------------------------------
// bf16-split tensor-core GEMM. CTA tile 128x128, 4 warps, warp tile 64x64,
// 2 CTAs/SM. Multi-problem via blockIdx.z + strides.
// loMask bit z: 1 -> full bf16x3 split (3 passes), 0 -> single bf16 pass.
// ---------------------------------------------------------------------------
__global__ __launch_bounds__(128, 2) void tc_gemm(
    const __nv_bfloat16* __restrict__ Ahi_, const __nv_bfloat16* __restrict__ Alo_,
    size_t aStr,
    const __nv_bfloat16* __restrict__ Bhi_, const __nv_bfloat16* __restrict__ Blo_,
    size_t bStr,
    const float* bias0, const float* bias1,
    float* C_, size_t cStr, int Mout, int loMask)
{
    extern __shared__ char smem[];
    const uint32_t sb = smem_u32(smem);
    const int z = blockIdx.z;
    const bool p3 = ((loMask >> z) & 1) != 0;
    const __nv_bfloat16* __restrict__ Ahi = Ahi_ + (size_t)z * aStr;
    const __nv_bfloat16* __restrict__ Alo = Alo_ + (size_t)z * aStr;
    const __nv_bfloat16* __restrict__ Bhi = Bhi_ + (size_t)z * bStr;
    const __nv_bfloat16* __restrict__ Blo = Blo_ + (size_t)z * bStr;
    const float* bias = (z == 0) ? bias0 : bias1;
    float* __restrict__ C = C_ + (size_t)z * cStr;

    const int tid = threadIdx.x;
    const int lane = tid & 31;
    const int warp = tid >> 5;          // 0..3
    const int brow = blockIdx.x * 128;
    const int bcol = blockIdx.y * 128;

    const int m0w = (warp >> 1) * 64;
    const int n0w = (warp & 1) * 64;
    const int lrow = lane & 15;
    const int lcol8 = (lane >> 4) << 3;

    float c[4][8][4];
    #pragma unroll
    for (int i = 0; i < 4; i++)
        #pragma unroll
        for (int j = 0; j < 8; j++)
            #pragma unroll
            for (int q = 0; q < 4; q++) c[i][j][q] = 0.f;

    // cp.async: 2048 x 16B atoms per stage over 128 threads -> 16 per thread
    auto issue = [&](int stage, int ch) {
        const int k0 = ch * 32;
        #pragma unroll
        for (int j = 0; j < 16; j++) {
            int gid = tid + 128 * j;
            int tl = gid >> 9;           // 0=Ahi 1=Alo 2=Bhi 3=Blo
            int t = gid & 511;
            int r = t >> 2, a = t & 3;
            const __nv_bfloat16* base =
                (tl == 0) ? Ahi : (tl == 1) ? Alo : (tl == 2) ? Bhi : Blo;
            int grow = ((tl < 2) ? brow : bcol) + r;
            const __nv_bfloat16* src = base + (size_t)grow * 1024 + k0 + a * 8;
            uint32_t dst = sb + (uint32_t)stage * STAGE_B + (uint32_t)tl * TILE_B
                         + (uint32_t)(r * 80 + a * 16);
            if (p3 || tl == 0 || tl == 2) cp16(dst, src);
        }
        cp_commit();
    };

    issue(0, 0);
    issue(1, 1);

    for (int ch = 0; ch < NCH; ch++) {
        cp_wait1();
        __syncthreads();

        const uint32_t base = sb + (uint32_t)(ch & 1) * STAGE_B;
        #pragma unroll
        for (int ss = 0; ss < 2; ss++) {
            const int kk = ss * 16;
            const uint32_t aoff = (uint32_t)((m0w + lrow) * TSTRIDE + kk + lcol8) * 2;
            const uint32_t boff = (uint32_t)((n0w + lrow) * TSTRIDE + kk + lcol8) * 2;
            const uint32_t fstep = (uint32_t)(16 * TSTRIDE) * 2;

            uint32_t aHi[4][4], bH[4][4];
            #pragma unroll
            for (int i = 0; i < 4; i++)
                ldm_x4(aHi[i], base + aoff + (uint32_t)i * fstep);
            #pragma unroll
            for (int g = 0; g < 4; g++)
                ldm_x4(bH[g], base + 2 * TILE_B + boff + (uint32_t)g * fstep);

            // pass 1: Ahi x Bhi (32 independent MMAs)
            #pragma unroll
            for (int g = 0; g < 4; g++)
                #pragma unroll
                for (int i = 0; i < 4; i++) {
                    mma_bf16(c[i][2 * g],     aHi[i], bH[g][0], bH[g][2]);
                    mma_bf16(c[i][2 * g + 1], aHi[i], bH[g][1], bH[g][3]);
                }

            if (p3) {
                // pass 2: Alo x Bhi, aLo loaded one-ahead (transient)
                uint32_t aL0[4], aL1[4];
                ldm_x4(aL0, base + TILE_B + aoff);
                #pragma unroll
                for (int i = 0; i < 4; i++) {
                    uint32_t* cur = (i & 1) ? aL1 : aL0;
                    uint32_t* nxt = (i & 1) ? aL0 : aL1;
                    if (i < 3)
                        ldm_x4(nxt, base + TILE_B + aoff + (uint32_t)(i + 1) * fstep);
                    #pragma unroll
                    for (int g = 0; g < 4; g++) {
                        mma_bf16(c[i][2 * g],     cur, bH[g][0], bH[g][2]);
                        mma_bf16(c[i][2 * g + 1], cur, bH[g][1], bH[g][3]);
                    }
                }
                // pass 3: Ahi x Blo, bL loaded one-ahead (transient)
                uint32_t bL0[4], bL1[4];
                ldm_x4(bL0, base + 3 * TILE_B + boff);
                #pragma unroll
                for (int g = 0; g < 4; g++) {
                    uint32_t* cur = (g & 1) ? bL1 : bL0;
                    uint32_t* nxt = (g & 1) ? bL0 : bL1;
                    if (g < 3)
                        ldm_x4(nxt, base + 3 * TILE_B + boff + (uint32_t)(g + 1) * fstep);
                    #pragma unroll
                    for (int i = 0; i < 4; i++) {
                        mma_bf16(c[i][2 * g],     aHi[i], cur[0], cur[2]);
                        mma_bf16(c[i][2 * g + 1], aHi[i], cur[1], cur[3]);
                    }
                }
            }
        }
        __syncthreads();
        if (ch + NSTAGE < NCH) issue(ch & 1, ch + NSTAGE);
        else cp_commit();
    }

    // epilogue: warp tile 64x64
    const int r = lane >> 2;
    const int cc = 2 * (lane & 3);
    #pragma unroll
    for (int i = 0; i < 4; i++) {
        int rowb = brow + m0w + i * 16;
        #pragma unroll
        for (int j = 0; j < 8; j++) {
            int col = bcol + n0w + j * 8 + cc;
            float b0 = 0.f, b1 = 0.f;
            if (bias) {
                if (col < Mout) b0 = bias[col];
                if (col + 1 < Mout) b1 = bias[col + 1];
            }
            float* p0 = C + (size_t)(rowb + r) * Mout + col;
            float* p1 = C + (size_t)(rowb + r + 8) * Mout + col;
            if (col + 1 < Mout) {
                p0[0] = c[i][j][0] + b0; p0[1] = c[i][j][1] + b1;
                p1[0] = c[i][j][2] + b0; p1[1] = c[i][j][3] + b1;
            } else if (col < Mout) {
                p0[0] = c[i][j][0] + b0;
                p1[0] = c[i][j][2] + b0;
            }
        }
    }
}

// ---------------------------------------------------------------------------
// all 15 square weight transpose+splits in one launch (z = net*5 + layer)
// lo written only for net 1 (slow) — v/p lo is never read by the x1 path
// ---------------------------------------------------------------------------
__global__ __launch_bounds__(256) void split_wt15_kernel(
    const float* Win0, const float* Win1, const float* Win2,
    const float* Whid0, const float* Whid1, const float* Whid2,
    __nv_bfloat16* Whi, __nv_bfloat16* Wlo)
{
    __shared__ float t[32][33];
    int z = blockIdx.z;
    int net = z / 5, layer = z % 5;
    const float* Win  = SEL3(net, Win0, Win1, Win2);
    const float* Whid = SEL3(net, Whid0, Whid1, Whid2);
    const float* W = (layer == 0) ? Win : (Whid + (size_t)(layer - 1) * Uc * Uc);
    __nv_bfloat16* dhi = Whi + (size_t)net * WSTR + (size_t)layer * Uc * Uc;
    __nv_bfloat16* dlo = Wlo + (size_t)net * WSTR + (size_t)layer * Uc * Uc;
    int k0 = blockIdx.x * 32, m0 = blockIdx.y * 32;
    int x = threadIdx.x, y = threadIdx.y;   // 32 x 8
    #pragma unroll
    for (int j = 0; j < 32; j += 8)
        t[y + j][x] = W[(size_t)(k0 + y + j) * Uc + m0 + x];
    __syncthreads();
    #pragma unroll
    for (int j = 0; j < 32; j += 8) {
        int m = m0 + y + j;
        float v = t[x][y + j];
        __nv_bfloat16 h, l;
        split1(v, h, l);
        dhi[(size_t)m * 1024 + k0 + x] = h;
        if (net == 1) dlo[(size_t)m * 1024 + k0 + x] = l;
    }
}

// head transpose + split: W[1024, M] -> [M,1024]
__global__ __launch_bounds__(256) void split_wt_kernel(
    const float* __restrict__ W, __nv_bfloat16* __restrict__ Whi,
    __nv_bfloat16* __restrict__ Wlo, int M)
{
    __shared__ float t[32][33];
    int k0 = blockIdx.x * 32, m0 = blockIdx.y * 32;
    int x = threadIdx.x, y = threadIdx.y;
    #pragma unroll
    for (int j = 0; j < 32; j += 8) {
        int m = m0 + x;
        if (m < M) t[y + j][x] = W[(size_t)(k0 + y + j) * M + m];
    }
    __syncthreads();
    #pragma unroll
    for (int j = 0; j < 32; j += 8) {
        int m = m0 + y + j;
        if (m < M) {
            float v = t[x][y + j];
            __nv_bfloat16 h, l;
            split1(v, h, l);
            Whi[(size_t)m * 1024 + k0 + x] = h;
            Wlo[(size_t)m * 1024 + k0 + x] = l;
        }
    }
}

// ---------------------------------------------------------------------------
// feat split
// ---------------------------------------------------------------------------
__global__ __launch_bounds__(256) void split_act_kernel(
    const float* __restrict__ X, __nv_bfloat16* __restrict__ Hi,
    __nv_bfloat16* __restrict__ Lo)
{
    size_t i = (size_t)blockIdx.x * 256 + threadIdx.x;
    float4 v = ((const float4*)X)[i];
    __nv_bfloat16 hx, hy, hz, hw, lx, ly, lz, lw;
    split1(v.x, hx, lx); split1(v.y, hy, ly);
    split1(v.z, hz, lz); split1(v.w, hw, lw);
    __nv_bfloat162 h0(hx, hy), h1(hz, hw), l0(lx, ly), l1(lz, lw);
    uint2 hp, lp;
    hp.x = *(uint32_t*)&h0; hp.y = *(uint32_t*)&h1;
    lp.x = *(uint32_t*)&l0; lp.y = *(uint32_t*)&l1;
    ((uint2*)Hi)[i] = hp;
    ((uint2*)Lo)[i] = lp;
}

// ---------------------------------------------------------------------------
// fused rmsnorm + silu + split for 3 nets; Lo written only for net 1 (slow)
// ---------------------------------------------------------------------------
__device__ __forceinline__ float silu_f(float z) { return z / (1.f + expf(-z)); }

__global__ __launch_bounds__(256) void rms3_kernel(
    const float* __restrict__ X,
    const float* g0, const float* g1, const float* g2,
    __nv_bfloat16* __restrict__ Hi, __nv_bfloat16* __restrict__ Lo)
{
    int net = blockIdx.y;
    int row = blockIdx.x;
    int t = threadIdx.x;
    const float* g = SEL3(net, g0, g1, g2);
    size_t off = (size_t)net * ASTR + (size_t)row * Uc;

    const float4* x4 = (const float4*)(X + off);
    float4 xv = x4[t];
    float ss = xv.x * xv.x + xv.y * xv.y + xv.z * xv.z + xv.w * xv.w;
    #pragma unroll
    for (int o = 16; o; o >>= 1) ss += __shfl_xor_sync(0xffffffffu, ss, o);
    __shared__ float sh[8];
    if ((t & 31) == 0) sh[t >> 5] = ss;
    __syncthreads();
    if (t < 32) {
        float v = (t < 8) ? sh[t] : 0.f;
        #pragma unroll
        for (int o = 4; o; o >>= 1) v += __shfl_xor_sync(0xffffffffu, v, o);
        if (t == 0) sh[0] = v;
    }
    __syncthreads();
    float r = rsqrtf(sh[0] * (1.0f / (float)Uc) + 1e-6f);
    float4 gv = ((const float4*)g)[t];
    float4 o;
    o.x = silu_f(xv.x * r * gv.x);
    o.y = silu_f(xv.y * r * gv.y);
    o.z = silu_f(xv.z * r * gv.z);
    o.w = silu_f(xv.w * r * gv.w);
    __nv_bfloat16 hx, hy, hz, hw, lx, ly, lz, lw;
    split1(o.x, hx, lx); split1(o.y, hy, ly);
    split1(o.z, hz, lz); split1(o.w, hw, lw);
    __nv_bfloat162 h0(hx, hy), h1(hz, hw), l0(lx, ly), l1(lz, lw);
    uint2 hp, lp;
    hp.x = *(uint32_t*)&h0; hp.y = *(uint32_t*)&h1;
    lp.x = *(uint32_t*)&l0; lp.y = *(uint32_t*)&l1;
    ((uint2*)(Hi + off))[t] = hp;
    if (net == 1) ((uint2*)(Lo + off))[t] = lp;
}

// ---------------------------------------------------------------------------
// symexp bins
// ---------------------------------------------------------------------------
__device__ __forceinline__ float bin_val(int i) {
    float u = -20.0f + (40.0f / 254.0f) * (float)i;
    return copysignf(expm1f(fabsf(u)), u);
}

// ---------------------------------------------------------------------------
// slow_mean
// ---------------------------------------------------------------------------
__global__ __launch_bounds__(256) void slowmean_kernel(
    const float* __restrict__ slog, float* __restrict__ smean)
{
    __shared__ float sred[8];
    __shared__ double dden[8], dnum[8];
    int row = blockIdx.x, tid = threadIdx.x;
    float lg = -3.4e38f, bn = 0.f;
    if (tid < NBc) {
        lg = slog[(size_t)row * NBc + tid];
        bn = bin_val(tid);
    }
    float m = lg;
    #pragma unroll
    for (int o = 16; o; o >>= 1) m = fmaxf(m, __shfl_xor_sync(0xffffffffu, m, o));
    if ((tid & 31) == 0) sred[tid >> 5] = m;
    __syncthreads();
    if (tid < 32) {
        float v = (tid < 8) ? sred[tid] : -3.4e38f;
        #pragma unroll
        for (int o = 4; o; o >>= 1) v = fmaxf(v, __shfl_xor_sync(0xffffffffu, v, o));
        if (tid == 0) sred[0] = v;
    }
    __syncthreads();
    float M = sred[0];
    float e = (tid < NBc) ? expf(lg - M) : 0.f;
    double den = (double)e;
    double num = (double)e * (double)bn;
    #pragma unroll
    for (int o = 16; o; o >>= 1) {
        den += __shfl_xor_sync(0xffffffffu, den, o);
        num += __shfl_xor_sync(0xffffffffu, num, o);
    }
    if ((tid & 31) == 0) { dden[tid >> 5] = den; dnum[tid >> 5] = num; }
    __syncthreads();
    if (tid == 0) {
        double D = 0, Nn = 0;
        #pragma unroll
        for (int i = 0; i < 8; i++) { D += dden[i]; Nn += dnum[i]; }
        smean[row] = (float)(Nn / D);
    }
}

// ---------------------------------------------------------------------------
// lambda-return scan
// ---------------------------------------------------------------------------
__global__ void lamret_kernel(
    const float* __restrict__ reward, const float* __restrict__ cont,
    const float* __restrict__ smean, float* __restrict__ ret, float* __restrict__ wgt)
{
    int b = threadIdx.x;
    if (b >= Bc) return;
    float acc = 1.f;
    for (int t = 0; t < TM1; t++) {
        acc *= cont[b * Tc + t];
        wgt[b * TM1 + t] = acc;
    }
    float r = smean[b * Tc + (Tc - 1)];
    for (int t = TM1 - 1; t >= 0; t--) {
        float live = cont[b * Tc + t + 1];
        float interm = reward[b * Tc + t + 1] + (1.f - LAM_C) * live * smean[b * Tc + t + 1];
        r = interm + live * LAM_C * r;
        ret[b * TM1 + t] = r;
    }
}

// ---------------------------------------------------------------------------
// exact 5th/95th percentile via 3-round histogram radix select (1 block)
// ---------------------------------------------------------------------------
__global__ __launch_bounds__(1024) void percentile_kernel(
    const float* __restrict__ ret, float* __restrict__ scale)
{
    __shared__ uint32_t hist[4][2048];
    __shared__ uint32_t pref[4];
    __shared__ uint32_t rem[4];
    __shared__ uint32_t vals[4];
    const int tid = threadIdx.x;
    const uint32_t RK0 = 1065u, RK1 = 1066u, RK2 = 20245u, RK3 = 20246u;

    for (int i = tid; i < 2048; i += 1024) hist[0][i] = 0;
    __syncthreads();
    for (int i = tid; i < NLOSS; i += 1024)
        atomicAdd(&hist[0][f2u(ret[i]) >> 21], 1u);
    __syncthreads();
    if (tid == 0) {
        uint32_t RK[4] = {RK0, RK1, RK2, RK3};
        for (int t = 0; t < 4; t++) {
            uint32_t cum = 0, r = RK[t];
            for (uint32_t b = 0; b < 2048; b++) {
                uint32_t c = hist[0][b];
                if (cum + c > r) { pref[t] = b << 21; rem[t] = r - cum; break; }
                cum += c;
            }
        }
    }
    __syncthreads();
    for (int i = tid; i < 4 * 2048; i += 1024) (&hist[0][0])[i] = 0;
    __syncthreads();
    for (int i = tid; i < NLOSS; i += 1024) {
        uint32_t u = f2u(ret[i]);
        uint32_t top = u & 0xFFE00000u;
        uint32_t mid = (u >> 10) & 2047u;
        #pragma unroll
        for (int t = 0; t < 4; t++)
            if (top == pref[t]) atomicAdd(&hist[t][mid], 1u);
    }
    __syncthreads();
    if (tid == 0) {
        for (int t = 0; t < 4; t++) {
            uint32_t cum = 0, r = rem[t];
            for (uint32_t b = 0; b < 2048; b++) {
                uint32_t c = hist[t][b];
                if (cum + c > r) { pref[t] |= b << 10; rem[t] = r - cum; break; }
                cum += c;
            }
        }
    }
    __syncthreads();
    for (int i = tid; i < 4 * 2048; i += 1024) (&hist[0][0])[i] = 0;
    __syncthreads();
    for (int i = tid; i < NLOSS; i += 1024) {
        uint32_t u = f2u(ret[i]);
        uint32_t top = u & 0xFFFFFC00u;
        uint32_t lo10 = u & 1023u;
        #pragma unroll
        for (int t = 0; t < 4; t++)
            if (top == pref[t]) atomicAdd(&hist[t][lo10], 1u);
    }
    __syncthreads();
    if (tid == 0) {
        for (int t = 0; t < 4; t++) {
            uint32_t cum = 0, r = rem[t];
            for (uint32_t b = 0; b < 1024; b++) {
                uint32_t c = hist[t][b];
                if (cum + c > r) { vals[t] = pref[t] | b; break; }
                cum += c;
            }
        }
        float v5a = u2f(vals[0]), v5b = u2f(vals[1]);
        float v95a = u2f(vals[2]), v95b = u2f(vals[3]);
        double p5 = 0.05 * (double)(NLOSS - 1);
        double p95 = 0.95 * (double)(NLOSS - 1);
        int i5 = (int)p5, i95 = (int)p95;
        float f5 = (float)(p5 - i5), f95 = (float)(p95 - i95);
        float lo = v5a + f5 * (v5b - v5a);
        float hi = v95a + f95 * (v95b - v95a);
        scale[0] = lo;
        scale[1] = hi;
        scale[2] = fmaxf(hi - lo, 1.0f);
    }
}

// ---------------------------------------------------------------------------
// per-token loss
// ---------------------------------------------------------------------------
__device__ __forceinline__ float twohot_nll(const float* svl, const float* sbins,
                                            float logZ, float y)
{
    y = fminf(fmaxf(y, sbins[0]), sbins[NBc - 1]);
    int lo = 0, hi = NBc - 1;
    while (hi > lo) {
        int mid = (lo + hi) >> 1;
        if (sbins[mid] >= y) hi = mid; else lo = mid + 1;
    }
    int k = hi - 1;
    if (k < 0) k = 0;
    if (k > NBc - 2) k = NBc - 2;
    float bl = sbins[k], bh = sbins[k + 1];
    float w = (y - bl) / (bh - bl);
    w = fminf(fmaxf(w, 0.f), 1.f);
    float l0 = svl[k] - logZ, l1 = svl[k + 1] - logZ;
    return -((1.f - w) * l0 + w * l1);
}

__global__ __launch_bounds__(256) void loss_kernel(
    const float* __restrict__ vlog, const float* __restrict__ plog,
    const float* __restrict__ smean, const float* __restrict__ ret,
    const float* __restrict__ wgt, const int* __restrict__ act,
    const float* __restrict__ scale, float* __restrict__ loss)
{
    __shared__ float sbins[NBc];
    __shared__ float svl[NBc];
    __shared__ float sred[8];
    __shared__ float sres[4];

    int i = blockIdx.x;
    int b = i / TM1, t = i - b * TM1;
    int row = b * Tc + t;
    int tid = threadIdx.x;

    if (tid < NBc) {
        sbins[tid] = bin_val(tid);
        svl[tid] = vlog[(size_t)row * NBc + tid];
    }
    __syncthreads();

    float v = (tid < NBc) ? svl[tid] : -3.4e38f;
    #pragma unroll
    for (int o = 16; o; o >>= 1) v = fmaxf(v, __shfl_xor_sync(0xffffffffu, v, o));
    if ((tid & 31) == 0) sred[tid >> 5] = v;
    __syncthreads();
    if (tid < 32) {
        float m = (tid < 8) ? sred[tid] : -3.4e38f;
        #pragma unroll
        for (int o = 4; o; o >>= 1) m = fmaxf(m, __shfl_xor_sync(0xffffffffu, m, o));
        if (tid == 0) sres[0] = m;
    }
    __syncthreads();
    float M = sres[0];
    float e = (tid < NBc) ? expf(svl[tid] - M) : 0.f;
    #pragma unroll
    for (int o = 16; o; o >>= 1) e += __shfl_xor_sync(0xffffffffu, e, o);
    if ((tid & 31) == 0) sred[tid >> 5] = e;
    __syncthreads();
    if (tid < 32) {
        float s = (tid < 8) ? sred[tid] : 0.f;
        #pragma unroll
        for (int o = 4; o; o >>= 1) s += __shfl_xor_sync(0xffffffffu, s, o);
        if (tid == 0) sres[0] = M + logf(s);
    }
    __syncthreads();
    float logZ = sres[0];

    if (tid < 32) {
        float p0 = plog[(size_t)row * Ac + tid];
        float p1 = plog[(size_t)row * Ac + tid + 32];
        float m = fmaxf(p0, p1);
        #pragma unroll
        for (int o = 16; o; o >>= 1) m = fmaxf(m, __shfl_xor_sync(0xffffffffu, m, o));
        float e0 = expf(p0 - m), e1 = expf(p1 - m);
        float s = e0 + e1;
        #pragma unroll
        for (int o = 16; o; o >>= 1) s += __shfl_xor_sync(0xffffffffu, s, o);
        float inv = 1.0f / s;
        float pr0 = 0.99f * e0 * inv + UNIMIX_A;
        float pr1 = 0.99f * e1 * inv + UNIMIX_A;
        float lp0 = logf(pr0), lp1 = logf(pr1);
        float entp = -(pr0 * lp0 + pr1 * lp1);
        #pragma unroll
        for (int o = 16; o; o >>= 1) entp += __shfl_xor_sync(0xffffffffu, entp, o);
        int a = act[row];
        float lpi = (a == tid) ? lp0 : ((a == tid + 32) ? lp1 : 0.f);
        #pragma unroll
        for (int o = 16; o; o >>= 1) lpi += __shfl_xor_sync(0xffffffffu, lpi, o);
        if (tid == 0) { sres[1] = entp; sres[2] = lpi; }
    }
    __syncthreads();

    if (tid == 0) {
        float reti = ret[i];
        float sm = smean[row];
        float rscale = scale[2];
        float adv = (reti - sm) / rscale;
        float wt = wgt[i];
        float pl = wt * -(sres[2] * adv + ACTENT_C * sres[1]);
        float vl = twohot_nll(svl, sbins, logZ, reti) + twohot_nll(svl, sbins, logZ, sm);
        loss[i] = pl + wt * vl;
    }
}

// ---------------------------------------------------------------------------
// final reduction
// ---------------------------------------------------------------------------
__global__ __launch_bounds__(1024) void reduce_kernel(
    const float* __restrict__ loss, float* __restrict__ out)
{
    __shared__ double sd[32];
    double s = 0.0;
    for (int i = threadIdx.x; i < NLOSS; i += 1024) s += (double)loss[i];
    #pragma unroll
    for (int o = 16; o; o >>= 1) s += __shfl_xor_sync(0xffffffffu, s, o);
    if ((threadIdx.x & 31) == 0) sd[threadIdx.x >> 5] = s;
    __syncthreads();
    if (threadIdx.x == 0) {
        double tot = 0.0;
        #pragma unroll
        for (int w = 0; w < 32; w++) tot += sd[w];
        out[0] = (float)(tot / (double)NLOSS);
    }
}

// ---------------------------------------------------------------------------
// host
// ---------------------------------------------------------------------------
extern "C" void kernel_launch(void* const* d_in, const int* in_sizes, int n_in,
                              void* d_out, int out_size)
{
    const float* feat   = (const float*)d_in[0];
    const float* reward = (const float*)d_in[1];
    const float* cont   = (const float*)d_in[2];
    const int*   act    = (const int*)  d_in[3];
    const float* pW_in  = (const float*)d_in[4];
    const float* pW_hid = (const float*)d_in[5];
    const float* p_gn   = (const float*)d_in[6];
    const float* pHw    = (const float*)d_in[7];
    const float* pHb    = (const float*)d_in[8];
    const float* vW_in  = (const float*)d_in[9];
    const float* vW_hid = (const float*)d_in[10];
    const float* v_gn   = (const float*)d_in[11];
    const float* vHw    = (const float*)d_in[12];
    const float* vHb    = (const float*)d_in[13];
    const float* sW_in  = (const float*)d_in[14];
    const float* sW_hid = (const float*)d_in[15];
    const float* s_gn   = (const float*)d_in[16];
    const float* sHw    = (const float*)d_in[17];
    const float* sHb    = (const float*)d_in[18];

    float *h0, *vslog, *plg, *smean, *ret, *wgt, *scale, *loss;
    __nv_bfloat16 *fhi, *flo, *a_hi, *a_lo, *w_hi, *w_lo;
    __nv_bfloat16 *hvs_hi, *hvs_lo, *hp_hi, *hp_lo;
    cudaGetSymbolAddress((void**)&h0, g_h0);
    cudaGetSymbolAddress((void**)&fhi, g_fhi);
    cudaGetSymbolAddress((void**)&flo, g_flo);
    cudaGetSymbolAddress((void**)&a_hi, g_a_hi);
    cudaGetSymbolAddress((void**)&a_lo, g_a_lo);
    cudaGetSymbolAddress((void**)&vslog, g_vslog);
    cudaGetSymbolAddress((void**)&plg, g_plog);
    cudaGetSymbolAddress((void**)&smean, g_smean);
    cudaGetSymbolAddress((void**)&ret, g_ret);
    cudaGetSymbolAddress((void**)&wgt, g_wgt);
    cudaGetSymbolAddress((void**)&scale, g_scale);
    cudaGetSymbolAddress((void**)&loss, g_loss);
    cudaGetSymbolAddress((void**)&w_hi, g_w_hi);
    cudaGetSymbolAddress((void**)&w_lo, g_w_lo);
    cudaGetSymbolAddress((void**)&hvs_hi, g_hvs_hi);
    cudaGetSymbolAddress((void**)&hvs_lo, g_hvs_lo);
    cudaGetSymbolAddress((void**)&hp_hi, g_hp_hi);
    cudaGetSymbolAddress((void**)&hp_lo, g_hp_lo);

    float* vlog = vslog;
    float* slog = vslog + LSTR;

    cudaFuncSetAttribute(tc_gemm, cudaFuncAttributeMaxDynamicSharedMemorySize, SMEM_B);

    dim3 tb(32, 8);
    split_wt15_kernel<<<dim3(32, 32, 15), tb>>>(
        vW_in, sW_in, pW_in, vW_hid, sW_hid, pW_hid, w_hi, w_lo);
    split_act_kernel<<<NTOK, 256>>>(feat, fhi, flo);
    split_wt_kernel<<<dim3(32, 2), tb>>>(pHw, hp_hi, hp_lo, Ac);

    // 5 fused layer GEMMs (net: 0=v x1, 1=s x3, 2=p x1) + fused rmsnorm
    for (int l = 0; l < 5; l++) {
        const __nv_bfloat16* Ah = (l == 0) ? fhi : a_hi;
        const __nv_bfloat16* Al = (l == 0) ? flo : a_lo;
        size_t aStr = (l == 0) ? 0 : ASTR;
        tc_gemm<<<dim3(NTOK / 128, 8, 3), 128, SMEM_B>>>(
            Ah, Al, aStr,
            w_hi + (size_t)l * Uc * Uc, w_lo + (size_t)l * Uc * Uc, WSTR,
            nullptr, nullptr, h0, ASTR, Uc, /*loMask=*/0b010);
        rms3_kernel<<<dim3(NTOK, 3), 256>>>(
            h0, v_gn + (size_t)l * Uc, s_gn + (size_t)l * Uc, p_gn + (size_t)l * Uc,
            a_hi, a_lo);
    }

    // head weight splits (needed only now)
    split_wt_kernel<<<dim3(32, 8), tb>>>(vHw, hvs_hi, hvs_lo, NBc);
    split_wt_kernel<<<dim3(32, 8), tb>>>(sHw, hvs_hi + HSTR, hvs_lo + HSTR, NBc);

    // heads: v+s fused (net 0 = v x1, net 1 = s x3), p separate (x1)
    tc_gemm<<<dim3(NTOK / 128, 2, 2), 128, SMEM_B>>>(
        a_hi, a_lo, ASTR, hvs_hi, hvs_lo, HSTR,
        vHb, sHb, vslog, LSTR, NBc, /*loMask=*/0b10);
    tc_gemm<<<dim3(NTOK / 128, 1, 1), 128, SMEM_B>>>(
        a_hi + 2 * ASTR, a_lo + 2 * ASTR, 0, hp_hi, hp_lo, 0,
        pHb, nullptr, plg, 0, Ac, /*loMask=*/0);

    slowmean_kernel<<<NTOK, 256>>>(slog, smean);
    lamret_kernel<<<1, 64>>>(reward, cont, smean, ret, wgt);
    percentile_kernel<<<1, 1024>>>(ret, scale);
    loss_kernel<<<NLOSS, 256>>>(vlog, plg, smean, ret, wgt, act, scale, loss);
    reduce_kernel<<<1, 1024>>>(loss, (float*)d_out);
}

// round 17
// speedup vs baseline: 1.5420x; 1.0233x over previous
#include <cuda_runtime.h>
#include <cuda_bf16.h>
#include <math.h>
#include <stdint.h>

// ---------------------------------------------------------------------------
// Problem constants
// ---------------------------------------------------------------------------
#define Bc    64
#define Tc    334
#define Fc    1024
#define Uc    1024
#define Ac    64
#define NBc   255
#define NTOK  (Bc * Tc)        // 21376 = 167 * 128
#define TM1   (Tc - 1)         // 333
#define NLOSS (Bc * TM1)       // 21312
#define LAM_C     0.95f
#define ACTENT_C  3e-4f
#define UNIMIX_A  0.00015625f  // 0.01 / 64
#define NCH   32               // K chunks of 32 (K = 1024)

// smem tile: 128 rows x 32 bf16, row stride 40 bf16 (80 B) -> conflict-free ldmatrix
#define TSTRIDE 40
#define TILE_B  (128 * TSTRIDE * 2)   // 10240 bytes
#define STAGE_B (4 * TILE_B)          // 40960 bytes (Ahi,Alo,Bhi,Blo)
#define NSTAGE  2
#define SMEM_B  (NSTAGE * STAGE_B)    // 81920 bytes -> 2 CTAs/SM

// net strides (elements)
#define ASTR ((size_t)NTOK * Uc)
#define WSTR ((size_t)5 * 1024 * 1024)
#define HSTR ((size_t)256 * 1024)
#define LSTR ((size_t)NTOK * NBc)

// ---------------------------------------------------------------------------
// Device scratch — single symbols, net index via stride
// ---------------------------------------------------------------------------
__device__ float g_h0[3 * ASTR];                 // fp32 h (used by s net, z=1)
__device__ __nv_bfloat16 g_hb[3 * ASTR];         // bf16 h (used by v/p nets)
__device__ __nv_bfloat16 g_fhi[ASTR];
__device__ __nv_bfloat16 g_flo[ASTR];
__device__ __nv_bfloat16 g_a_hi[3 * ASTR];
__device__ __nv_bfloat16 g_a_lo[3 * ASTR];
__device__ float g_vslog[2 * LSTR];              // [0]=vlog, [1]=slog
__device__ float g_plog[(size_t)NTOK * Ac];
__device__ float g_smean[NTOK];
__device__ float g_ret[NLOSS];
__device__ float g_wgt[NLOSS];
__device__ float g_scale[4];
__device__ float g_loss[NLOSS];
// split K-major weights (bf16 hi/lo). Head pad rows never written -> stay 0.
__device__ __nv_bfloat16 g_w_hi[3 * WSTR];
__device__ __nv_bfloat16 g_w_lo[3 * WSTR];
__device__ __nv_bfloat16 g_hvs_hi[2 * HSTR];
__device__ __nv_bfloat16 g_hvs_lo[2 * HSTR];
__device__ __nv_bfloat16 g_hp_hi[128 * 1024];
__device__ __nv_bfloat16 g_hp_lo[128 * 1024];

// ---------------------------------------------------------------------------
// helpers
// ---------------------------------------------------------------------------
__device__ __forceinline__ uint32_t smem_u32(const void* p) {
    uint32_t a;
    asm("{ .reg .u64 t; cvta.to.shared.u64 t, %1; cvt.u32.u64 %0, t; }" : "=r"(a) : "l"(p));
    return a;
}
__device__ __forceinline__ void ldm_x4(uint32_t* f, uint32_t addr) {
    asm volatile("ldmatrix.sync.aligned.m8n8.x4.shared.b16 {%0,%1,%2,%3}, [%4];"
                 : "=r"(f[0]), "=r"(f[1]), "=r"(f[2]), "=r"(f[3]) : "r"(addr));
}
__device__ __forceinline__ void mma_bf16(float* c, const uint32_t* a,
                                         uint32_t b0, uint32_t b1) {
    asm volatile(
        "mma.sync.aligned.m16n8k16.row.col.f32.bf16.bf16.f32 "
        "{%0,%1,%2,%3}, {%4,%5,%6,%7}, {%8,%9}, {%0,%1,%2,%3};"
        : "+f"(c[0]), "+f"(c[1]), "+f"(c[2]), "+f"(c[3])
        : "r"(a[0]), "r"(a[1]), "r"(a[2]), "r"(a[3]), "r"(b0), "r"(b1));
}
__device__ __forceinline__ void cp16(uint32_t dst, const void* src) {
    asm volatile("cp.async.ca.shared.global [%0], [%1], 16;" :: "r"(dst), "l"(src));
}
__device__ __forceinline__ void cp_commit() {
    asm volatile("cp.async.commit_group;" ::: "memory");
}
__device__ __forceinline__ void cp_wait1() {
    asm volatile("cp.async.wait_group 1;" ::: "memory");
}
__device__ __forceinline__ void split1(float v, __nv_bfloat16& h, __nv_bfloat16& l) {
    h = __float2bfloat16(v);
    l = __float2bfloat16(v - __bfloat162float(h));
}
#define SEL3(z, a, b, cc) ((z) == 0 ? (a) : (z) == 1 ? (b) : (cc))

// order-preserving float<->uint for radix select
__device__ __forceinline__ uint32_t f2u(float f) {
    uint32_t b = __float_as_uint(f);
    return (b & 0x80000000u) ? ~b : (b | 0x80000000u);
}
__device__ __forceinline__ float u2f(uint32_t u) {
    uint32_t b = (u & 0x80000000u) ? (u & 0x7fffffffu) : ~u;
    return __uint_as_float(b);
}

// ---------------------------------------------------------------------------
// bf16-split tensor-core GEMM. CTA tile 128x128, 4 warps, warp tile 64x64,
// 2 CTAs/SM. Multi-problem via blockIdx.z + strides (z-major keeps L2 reuse).
// loMask bit z: 1 -> full bf16x3 split (3 passes), 0 -> single bf16 pass.
// bfMask bit z: 1 -> write bf16 output to Cb_ (no bias), 0 -> fp32 to C_.
// ---------------------------------------------------------------------------
__global__ __launch_bounds__(128, 2) void tc_gemm(
    const __nv_bfloat16* __restrict__ Ahi_, const __nv_bfloat16* __restrict__ Alo_,
    size_t aStr,
    const __nv_bfloat16* __restrict__ Bhi_, const __nv_bfloat16* __restrict__ Blo_,
    size_t bStr,
    const float* bias0, const float* bias1,
    float* C_, __nv_bfloat16* Cb_, size_t cStr, int Mout,
    int loMask, int bfMask)
{
    extern __shared__ char smem[];
    const uint32_t sb = smem_u32(smem);
    const int z = blockIdx.z;
    const bool p3 = ((loMask >> z) & 1) != 0;
    const bool obf = ((bfMask >> z) & 1) != 0;
    const __nv_bfloat16* __restrict__ Ahi = Ahi_ + (size_t)z * aStr;
    const __nv_bfloat16* __restrict__ Alo = Alo_ + (size_t)z * aStr;
    const __nv_bfloat16* __restrict__ Bhi = Bhi_ + (size_t)z * bStr;
    const __nv_bfloat16* __restrict__ Blo = Blo_ + (size_t)z * bStr;
    const float* bias = (z == 0) ? bias0 : bias1;
    float* __restrict__ C = C_ + (size_t)z * cStr;
    __nv_bfloat16* __restrict__ Cb = Cb_ + (size_t)z * cStr;

    const int tid = threadIdx.x;
    const int lane = tid & 31;
    const int warp = tid >> 5;          // 0..3
    const int brow = blockIdx.x * 128;
    const int bcol = blockIdx.y * 128;

    const int m0w = (warp >> 1) * 64;
    const int n0w = (warp & 1) * 64;
    const int lrow = lane & 15;
    const int lcol8 = (lane >> 4) << 3;

    float c[4][8][4];
    #pragma unroll
    for (int i = 0; i < 4; i++)
        #pragma unroll
        for (int j = 0; j < 8; j++)
            #pragma unroll
            for (int q = 0; q < 4; q++) c[i][j][q] = 0.f;

    // cp.async: 2048 x 16B atoms per stage over 128 threads -> 16 per thread
    auto issue = [&](int stage, int ch) {
        const int k0 = ch * 32;
        #pragma unroll
        for (int j = 0; j < 16; j++) {
            int gid = tid + 128 * j;
            int tl = gid >> 9;           // 0=Ahi 1=Alo 2=Bhi 3=Blo
            int t = gid & 511;
            int r = t >> 2, a = t & 3;
            const __nv_bfloat16* base =
                (tl == 0) ? Ahi : (tl == 1) ? Alo : (tl == 2) ? Bhi : Blo;
            int grow = ((tl < 2) ? brow : bcol) + r;
            const __nv_bfloat16* src = base + (size_t)grow * 1024 + k0 + a * 8;
            uint32_t dst = sb + (uint32_t)stage * STAGE_B + (uint32_t)tl * TILE_B
                         + (uint32_t)(r * 80 + a * 16);
            if (p3 || tl == 0 || tl == 2) cp16(dst, src);
        }
        cp_commit();
    };

    issue(0, 0);
    issue(1, 1);

    for (int ch = 0; ch < NCH; ch++) {
        cp_wait1();
        __syncthreads();

        const uint32_t base = sb + (uint32_t)(ch & 1) * STAGE_B;
        #pragma unroll
        for (int ss = 0; ss < 2; ss++) {
            const int kk = ss * 16;
            const uint32_t aoff = (uint32_t)((m0w + lrow) * TSTRIDE + kk + lcol8) * 2;
            const uint32_t boff = (uint32_t)((n0w + lrow) * TSTRIDE + kk + lcol8) * 2;
            const uint32_t fstep = (uint32_t)(16 * TSTRIDE) * 2;

            uint32_t aHi[4][4], bH[4][4];
            #pragma unroll
            for (int i = 0; i < 4; i++)
                ldm_x4(aHi[i], base + aoff + (uint32_t)i * fstep);
            #pragma unroll
            for (int g = 0; g < 4; g++)
                ldm_x4(bH[g], base + 2 * TILE_B + boff + (uint32_t)g * fstep);

            // pass 1: Ahi x Bhi (32 independent MMAs)
            #pragma unroll
            for (int g = 0; g < 4; g++)
                #pragma unroll
                for (int i = 0; i < 4; i++) {
                    mma_bf16(c[i][2 * g],     aHi[i], bH[g][0], bH[g][2]);
                    mma_bf16(c[i][2 * g + 1], aHi[i], bH[g][1], bH[g][3]);
                }

            if (p3) {
                // pass 2: Alo x Bhi, aLo loaded one-ahead (transient)
                uint32_t aL0[4], aL1[4];
                ldm_x4(aL0, base + TILE_B + aoff);
                #pragma unroll
                for (int i = 0; i < 4; i++) {
                    uint32_t* cur = (i & 1) ? aL1 : aL0;
                    uint32_t* nxt = (i & 1) ? aL0 : aL1;
                    if (i < 3)
                        ldm_x4(nxt, base + TILE_B + aoff + (uint32_t)(i + 1) * fstep);
                    #pragma unroll
                    for (int g = 0; g < 4; g++) {
                        mma_bf16(c[i][2 * g],     cur, bH[g][0], bH[g][2]);
                        mma_bf16(c[i][2 * g + 1], cur, bH[g][1], bH[g][3]);
                    }
                }
                // pass 3: Ahi x Blo, bL loaded one-ahead (transient)
                uint32_t bL0[4], bL1[4];
                ldm_x4(bL0, base + 3 * TILE_B + boff);
                #pragma unroll
                for (int g = 0; g < 4; g++) {
                    uint32_t* cur = (g & 1) ? bL1 : bL0;
                    uint32_t* nxt = (g & 1) ? bL0 : bL1;
                    if (g < 3)
                        ldm_x4(nxt, base + 3 * TILE_B + boff + (uint32_t)(g + 1) * fstep);
                    #pragma unroll
                    for (int i = 0; i < 4; i++) {
                        mma_bf16(c[i][2 * g],     aHi[i], cur[0], cur[2]);
                        mma_bf16(c[i][2 * g + 1], aHi[i], cur[1], cur[3]);
                    }
                }
            }
        }
        __syncthreads();
        if (ch + NSTAGE < NCH) issue(ch & 1, ch + NSTAGE);
        else cp_commit();
    }

    // epilogue: warp tile 64x64
    const int r = lane >> 2;
    const int cc = 2 * (lane & 3);
    if (obf) {
        // bf16 output (layer h for v/p nets; bias always null here, Mout mult of 2)
        #pragma unroll
        for (int i = 0; i < 4; i++) {
            int rowb = brow + m0w + i * 16;
            #pragma unroll
            for (int j = 0; j < 8; j++) {
                int col = bcol + n0w + j * 8 + cc;
                __nv_bfloat162 v0(__float2bfloat16(c[i][j][0]),
                                  __float2bfloat16(c[i][j][1]));
                __nv_bfloat162 v1(__float2bfloat16(c[i][j][2]),
                                  __float2bfloat16(c[i][j][3]));
                *(__nv_bfloat162*)(Cb + (size_t)(rowb + r) * Mout + col) = v0;
                *(__nv_bfloat162*)(Cb + (size_t)(rowb + r + 8) * Mout + col) = v1;
            }
        }
    } else {
        #pragma unroll
        for (int i = 0; i < 4; i++) {
            int rowb = brow + m0w + i * 16;
            #pragma unroll
            for (int j = 0; j < 8; j++) {
                int col = bcol + n0w + j * 8 + cc;
                float b0 = 0.f, b1 = 0.f;
                if (bias) {
                    if (col < Mout) b0 = bias[col];
                    if (col + 1 < Mout) b1 = bias[col + 1];
                }
                float* p0 = C + (size_t)(rowb + r) * Mout + col;
                float* p1 = C + (size_t)(rowb + r + 8) * Mout + col;
                if (col + 1 < Mout) {
                    p0[0] = c[i][j][0] + b0; p0[1] = c[i][j][1] + b1;
                    p1[0] = c[i][j][2] + b0; p1[1] = c[i][j][3] + b1;
                } else if (col < Mout) {
                    p0[0] = c[i][j][0] + b0;
                    p1[0] = c[i][j][2] + b0;
                }
            }
        }
    }
}

// ---------------------------------------------------------------------------
// all 15 square weight transpose+splits in one launch (z = net*5 + layer)
// lo written only for net 1 (slow) — v/p lo is never read
// ---------------------------------------------------------------------------
__global__ __launch_bounds__(256) void split_wt15_kernel(
    const float* Win0, const float* Win1, const float* Win2,
    const float* Whid0, const float* Whid1, const float* Whid2,
    __nv_bfloat16* Whi, __nv_bfloat16* Wlo)
{
    __shared__ float t[32][33];
    int z = blockIdx.z;
    int net = z / 5, layer = z % 5;
    const float* Win  = SEL3(net, Win0, Win1, Win2);
    const float* Whid = SEL3(net, Whid0, Whid1, Whid2);
    const float* W = (layer == 0) ? Win : (Whid + (size_t)(layer - 1) * Uc * Uc);
    __nv_bfloat16* dhi = Whi + (size_t)net * WSTR + (size_t)layer * Uc * Uc;
    __nv_bfloat16* dlo = Wlo + (size_t)net * WSTR + (size_t)layer * Uc * Uc;
    int k0 = blockIdx.x * 32, m0 = blockIdx.y * 32;
    int x = threadIdx.x, y = threadIdx.y;   // 32 x 8
    #pragma unroll
    for (int j = 0; j < 32; j += 8)
        t[y + j][x] = W[(size_t)(k0 + y + j) * Uc + m0 + x];
    __syncthreads();
    #pragma unroll
    for (int j = 0; j < 32; j += 8) {
        int m = m0 + y + j;
        float v = t[x][y + j];
        __nv_bfloat16 h, l;
        split1(v, h, l);
        dhi[(size_t)m * 1024 + k0 + x] = h;
        if (net == 1) dlo[(size_t)m * 1024 + k0 + x] = l;
    }
}

// head transpose + split: W[1024, M] -> [M,1024]
__global__ __launch_bounds__(256) void split_wt_kernel(
    const float* __restrict__ W, __nv_bfloat16* __restrict__ Whi,
    __nv_bfloat16* __restrict__ Wlo, int M)
{
    __shared__ float t[32][33];
    int k0 = blockIdx.x * 32, m0 = blockIdx.y * 32;
    int x = threadIdx.x, y = threadIdx.y;
    #pragma unroll
    for (int j = 0; j < 32; j += 8) {
        int m = m0 + x;
        if (m < M) t[y + j][x] = W[(size_t)(k0 + y + j) * M + m];
    }
    __syncthreads();
    #pragma unroll
    for (int j = 0; j < 32; j += 8) {
        int m = m0 + y + j;
        if (m < M) {
            float v = t[x][y + j];
            __nv_bfloat16 h, l;
            split1(v, h, l);
            Whi[(size_t)m * 1024 + k0 + x] = h;
            Wlo[(size_t)m * 1024 + k0 + x] = l;
        }
    }
}

// ---------------------------------------------------------------------------
// feat split
// ---------------------------------------------------------------------------
__global__ __launch_bounds__(256) void split_act_kernel(
    const float* __restrict__ X, __nv_bfloat16* __restrict__ Hi,
    __nv_bfloat16* __restrict__ Lo)
{
    size_t i = (size_t)blockIdx.x * 256 + threadIdx.x;
    float4 v = ((const float4*)X)[i];
    __nv_bfloat16 hx, hy, hz, hw, lx, ly, lz, lw;
    split1(v.x, hx, lx); split1(v.y, hy, ly);
    split1(v.z, hz, lz); split1(v.w, hw, lw);
    __nv_bfloat162 h0(hx, hy), h1(hz, hw), l0(lx, ly), l1(lz, lw);
    uint2 hp, lp;
    hp.x = *(uint32_t*)&h0; hp.y = *(uint32_t*)&h1;
    lp.x = *(uint32_t*)&l0; lp.y = *(uint32_t*)&l1;
    ((uint2*)Hi)[i] = hp;
    ((uint2*)Lo)[i] = lp;
}

// ---------------------------------------------------------------------------
// fused rmsnorm + silu + split for 3 nets; net 1 reads fp32 Xf, nets 0/2 read
// bf16 Xb; Lo written only for net 1 (slow)
// ---------------------------------------------------------------------------
__device__ __forceinline__ float silu_f(float z) { return z / (1.f + expf(-z)); }

__global__ __launch_bounds__(256) void rms3_kernel(
    const float* __restrict__ Xf, const __nv_bfloat16* __restrict__ Xb,
    const float* g0, const float* g1, const float* g2,
    __nv_bfloat16* __restrict__ Hi, __nv_bfloat16* __restrict__ Lo)
{
    int net = blockIdx.y;
    int row = blockIdx.x;
    int t = threadIdx.x;
    const float* g = SEL3(net, g0, g1, g2);
    size_t off = (size_t)net * ASTR + (size_t)row * Uc;

    float4 xv;
    if (net == 1) {
        xv = ((const float4*)(Xf + off))[t];
    } else {
        uint2 u = ((const uint2*)(Xb + off))[t];
        __nv_bfloat162 b0 = *(__nv_bfloat162*)&u.x;
        __nv_bfloat162 b1 = *(__nv_bfloat162*)&u.y;
        xv.x = __bfloat162float(b0.x);
        xv.y = __bfloat162float(b0.y);
        xv.z = __bfloat162float(b1.x);
        xv.w = __bfloat162float(b1.y);
    }
    float ss = xv.x * xv.x + xv.y * xv.y + xv.z * xv.z + xv.w * xv.w;
    #pragma unroll
    for (int o = 16; o; o >>= 1) ss += __shfl_xor_sync(0xffffffffu, ss, o);
    __shared__ float sh[8];
    if ((t & 31) == 0) sh[t >> 5] = ss;
    __syncthreads();
    if (t < 32) {
        float v = (t < 8) ? sh[t] : 0.f;
        #pragma unroll
        for (int o = 4; o; o >>= 1) v += __shfl_xor_sync(0xffffffffu, v, o);
        if (t == 0) sh[0] = v;
    }
    __syncthreads();
    float r = rsqrtf(sh[0] * (1.0f / (float)Uc) + 1e-6f);
    float4 gv = ((const float4*)g)[t];
    float4 o;
    o.x = silu_f(xv.x * r * gv.x);
    o.y = silu_f(xv.y * r * gv.y);
    o.z = silu_f(xv.z * r * gv.z);
    o.w = silu_f(xv.w * r * gv.w);
    __nv_bfloat16 hx, hy, hz, hw, lx, ly, lz, lw;
    split1(o.x, hx, lx); split1(o.y, hy, ly);
    split1(o.z, hz, lz); split1(o.w, hw, lw);
    __nv_bfloat162 h0(hx, hy), h1(hz, hw), l0(lx, ly), l1(lz, lw);
    uint2 hp, lp;
    hp.x = *(uint32_t*)&h0; hp.y = *(uint32_t*)&h1;
    lp.x = *(uint32_t*)&l0; lp.y = *(uint32_t*)&l1;
    ((uint2*)(Hi + off))[t] = hp;
    if (net == 1) ((uint2*)(Lo + off))[t] = lp;
}

// ---------------------------------------------------------------------------
// symexp bins
// ---------------------------------------------------------------------------
__device__ __forceinline__ float bin_val(int i) {
    float u = -20.0f + (40.0f / 254.0f) * (float)i;
    return copysignf(expm1f(fabsf(u)), u);
}

// ---------------------------------------------------------------------------
// slow_mean
// ---------------------------------------------------------------------------
__global__ __launch_bounds__(256) void slowmean_kernel(
    const float* __restrict__ slog, float* __restrict__ smean)
{
    __shared__ float sred[8];
    __shared__ double dden[8], dnum[8];
    int row = blockIdx.x, tid = threadIdx.x;
    float lg = -3.4e38f, bn = 0.f;
    if (tid < NBc) {
        lg = slog[(size_t)row * NBc + tid];
        bn = bin_val(tid);
    }
    float m = lg;
    #pragma unroll
    for (int o = 16; o; o >>= 1) m = fmaxf(m, __shfl_xor_sync(0xffffffffu, m, o));
    if ((tid & 31) == 0) sred[tid >> 5] = m;
    __syncthreads();
    if (tid < 32) {
        float v = (tid < 8) ? sred[tid] : -3.4e38f;
        #pragma unroll
        for (int o = 4; o; o >>= 1) v = fmaxf(v, __shfl_xor_sync(0xffffffffu, v, o));
        if (tid == 0) sred[0] = v;
    }
    __syncthreads();
    float M = sred[0];
    float e = (tid < NBc) ? expf(lg - M) : 0.f;
    double den = (double)e;
    double num = (double)e * (double)bn;
    #pragma unroll
    for (int o = 16; o; o >>= 1) {
        den += __shfl_xor_sync(0xffffffffu, den, o);
        num += __shfl_xor_sync(0xffffffffu, num, o);
    }
    if ((tid & 31) == 0) { dden[tid >> 5] = den; dnum[tid >> 5] = num; }
    __syncthreads();
    if (tid == 0) {
        double D = 0, Nn = 0;
        #pragma unroll
        for (int i = 0; i < 8; i++) { D += dden[i]; Nn += dnum[i]; }
        smean[row] = (float)(Nn / D);
    }
}

// ---------------------------------------------------------------------------
// lambda-return scan
// ---------------------------------------------------------------------------
__global__ void lamret_kernel(
    const float* __restrict__ reward, const float* __restrict__ cont,
    const float* __restrict__ smean, float* __restrict__ ret, float* __restrict__ wgt)
{
    int b = threadIdx.x;
    if (b >= Bc) return;
    float acc = 1.f;
    for (int t = 0; t < TM1; t++) {
        acc *= cont[b * Tc + t];
        wgt[b * TM1 + t] = acc;
    }
    float r = smean[b * Tc + (Tc - 1)];
    for (int t = TM1 - 1; t >= 0; t--) {
        float live = cont[b * Tc + t + 1];
        float interm = reward[b * Tc + t + 1] + (1.f - LAM_C) * live * smean[b * Tc + t + 1];
        r = interm + live * LAM_C * r;
        ret[b * TM1 + t] = r;
    }
}

// ---------------------------------------------------------------------------
// exact 5th/95th percentile via 3-round histogram radix select (1 block)
// ---------------------------------------------------------------------------
__global__ __launch_bounds__(1024) void percentile_kernel(
    const float* __restrict__ ret, float* __restrict__ scale)
{
    __shared__ uint32_t hist[4][2048];
    __shared__ uint32_t pref[4];
    __shared__ uint32_t rem[4];
    __shared__ uint32_t vals[4];
    const int tid = threadIdx.x;
    const uint32_t RK0 = 1065u, RK1 = 1066u, RK2 = 20245u, RK3 = 20246u;

    for (int i = tid; i < 2048; i += 1024) hist[0][i] = 0;
    __syncthreads();
    for (int i = tid; i < NLOSS; i += 1024)
        atomicAdd(&hist[0][f2u(ret[i]) >> 21], 1u);
    __syncthreads();
    if (tid == 0) {
        uint32_t RK[4] = {RK0, RK1, RK2, RK3};
        for (int t = 0; t < 4; t++) {
            uint32_t cum = 0, r = RK[t];
            for (uint32_t b = 0; b < 2048; b++) {
                uint32_t c = hist[0][b];
                if (cum + c > r) { pref[t] = b << 21; rem[t] = r - cum; break; }
                cum += c;
            }
        }
    }
    __syncthreads();
    for (int i = tid; i < 4 * 2048; i += 1024) (&hist[0][0])[i] = 0;
    __syncthreads();
    for (int i = tid; i < NLOSS; i += 1024) {
        uint32_t u = f2u(ret[i]);
        uint32_t top = u & 0xFFE00000u;
        uint32_t mid = (u >> 10) & 2047u;
        #pragma unroll
        for (int t = 0; t < 4; t++)
            if (top == pref[t]) atomicAdd(&hist[t][mid], 1u);
    }
    __syncthreads();
    if (tid == 0) {
        for (int t = 0; t < 4; t++) {
            uint32_t cum = 0, r = rem[t];
            for (uint32_t b = 0; b < 2048; b++) {
                uint32_t c = hist[t][b];
                if (cum + c > r) { pref[t] |= b << 10; rem[t] = r - cum; break; }
                cum += c;
            }
        }
    }
    __syncthreads();
    for (int i = tid; i < 4 * 2048; i += 1024) (&hist[0][0])[i] = 0;
    __syncthreads();
    for (int i = tid; i < NLOSS; i += 1024) {
        uint32_t u = f2u(ret[i]);
        uint32_t top = u & 0xFFFFFC00u;
        uint32_t lo10 = u & 1023u;
        #pragma unroll
        for (int t = 0; t < 4; t++)
            if (top == pref[t]) atomicAdd(&hist[t][lo10], 1u);
    }
    __syncthreads();
    if (tid == 0) {
        for (int t = 0; t < 4; t++) {
            uint32_t cum = 0, r = rem[t];
            for (uint32_t b = 0; b < 1024; b++) {
                uint32_t c = hist[t][b];
                if (cum + c > r) { vals[t] = pref[t] | b; break; }
                cum += c;
            }
        }
        float v5a = u2f(vals[0]), v5b = u2f(vals[1]);
        float v95a = u2f(vals[2]), v95b = u2f(vals[3]);
        double p5 = 0.05 * (double)(NLOSS - 1);
        double p95 = 0.95 * (double)(NLOSS - 1);
        int i5 = (int)p5, i95 = (int)p95;
        float f5 = (float)(p5 - i5), f95 = (float)(p95 - i95);
        float lo = v5a + f5 * (v5b - v5a);
        float hi = v95a + f95 * (v95b - v95a);
        scale[0] = lo;
        scale[1] = hi;
        scale[2] = fmaxf(hi - lo, 1.0f);
    }
}

// ---------------------------------------------------------------------------
// per-token loss
// ---------------------------------------------------------------------------
__device__ __forceinline__ float twohot_nll(const float* svl, const float* sbins,
                                            float logZ, float y)
{
    y = fminf(fmaxf(y, sbins[0]), sbins[NBc - 1]);
    int lo = 0, hi = NBc - 1;
    while (hi > lo) {
        int mid = (lo + hi) >> 1;
        if (sbins[mid] >= y) hi = mid; else lo = mid + 1;
    }
    int k = hi - 1;
    if (k < 0) k = 0;
    if (k > NBc - 2) k = NBc - 2;
    float bl = sbins[k], bh = sbins[k + 1];
    float w = (y - bl) / (bh - bl);
    w = fminf(fmaxf(w, 0.f), 1.f);
    float l0 = svl[k] - logZ, l1 = svl[k + 1] - logZ;
    return -((1.f - w) * l0 + w * l1);
}

__global__ __launch_bounds__(256) void loss_kernel(
    const float* __restrict__ vlog, const float* __restrict__ plog,
    const float* __restrict__ smean, const float* __restrict__ ret,
    const float* __restrict__ wgt, const int* __restrict__ act,
    const float* __restrict__ scale, float* __restrict__ loss)
{
    __shared__ float sbins[NBc];
    __shared__ float svl[NBc];
    __shared__ float sred[8];
    __shared__ float sres[4];

    int i = blockIdx.x;
    int b = i / TM1, t = i - b * TM1;
    int row = b * Tc + t;
    int tid = threadIdx.x;

    if (tid < NBc) {
        sbins[tid] = bin_val(tid);
        svl[tid] = vlog[(size_t)row * NBc + tid];
    }
    __syncthreads();

    float v = (tid < NBc) ? svl[tid] : -3.4e38f;
    #pragma unroll
    for (int o = 16; o; o >>= 1) v = fmaxf(v, __shfl_xor_sync(0xffffffffu, v, o));
    if ((tid & 31) == 0) sred[tid >> 5] = v;
    __syncthreads();
    if (tid < 32) {
        float m = (tid < 8) ? sred[tid] : -3.4e38f;
        #pragma unroll
        for (int o = 4; o; o >>= 1) m = fmaxf(m, __shfl_xor_sync(0xffffffffu, m, o));
        if (tid == 0) sres[0] = m;
    }
    __syncthreads();
    float M = sres[0];
    float e = (tid < NBc) ? expf(svl[tid] - M) : 0.f;
    #pragma unroll
    for (int o = 16; o; o >>= 1) e += __shfl_xor_sync(0xffffffffu, e, o);
    if ((tid & 31) == 0) sred[tid >> 5] = e;
    __syncthreads();
    if (tid < 32) {
        float s = (tid < 8) ? sred[tid] : 0.f;
        #pragma unroll
        for (int o = 4; o; o >>= 1) s += __shfl_xor_sync(0xffffffffu, s, o);
        if (tid == 0) sres[0] = M + logf(s);
    }
    __syncthreads();
    float logZ = sres[0];

    if (tid < 32) {
        float p0 = plog[(size_t)row * Ac + tid];
        float p1 = plog[(size_t)row * Ac + tid + 32];
        float m = fmaxf(p0, p1);
        #pragma unroll
        for (int o = 16; o; o >>= 1) m = fmaxf(m, __shfl_xor_sync(0xffffffffu, m, o));
        float e0 = expf(p0 - m), e1 = expf(p1 - m);
        float s = e0 + e1;
        #pragma unroll
        for (int o = 16; o; o >>= 1) s += __shfl_xor_sync(0xffffffffu, s, o);
        float inv = 1.0f / s;
        float pr0 = 0.99f * e0 * inv + UNIMIX_A;
        float pr1 = 0.99f * e1 * inv + UNIMIX_A;
        float lp0 = logf(pr0), lp1 = logf(pr1);
        float entp = -(pr0 * lp0 + pr1 * lp1);
        #pragma unroll
        for (int o = 16; o; o >>= 1) entp += __shfl_xor_sync(0xffffffffu, entp, o);
        int a = act[row];
        float lpi = (a == tid) ? lp0 : ((a == tid + 32) ? lp1 : 0.f);
        #pragma unroll
        for (int o = 16; o; o >>= 1) lpi += __shfl_xor_sync(0xffffffffu, lpi, o);
        if (tid == 0) { sres[1] = entp; sres[2] = lpi; }
    }
    __syncthreads();

    if (tid == 0) {
        float reti = ret[i];
        float sm = smean[row];
        float rscale = scale[2];
        float adv = (reti - sm) / rscale;
        float wt = wgt[i];
        float pl = wt * -(sres[2] * adv + ACTENT_C * sres[1]);
        float vl = twohot_nll(svl, sbins, logZ, reti) + twohot_nll(svl, sbins, logZ, sm);
        loss[i] = pl + wt * vl;
    }
}

// ---------------------------------------------------------------------------
// final reduction
// ---------------------------------------------------------------------------
__global__ __launch_bounds__(1024) void reduce_kernel(
    const float* __restrict__ loss, float* __restrict__ out)
{
    __shared__ double sd[32];
    double s = 0.0;
    for (int i = threadIdx.x; i < NLOSS; i += 1024) s += (double)loss[i];
    #pragma unroll
    for (int o = 16; o; o >>= 1) s += __shfl_xor_sync(0xffffffffu, s, o);
    if ((threadIdx.x & 31) == 0) sd[threadIdx.x >> 5] = s;
    __syncthreads();
    if (threadIdx.x == 0) {
        double tot = 0.0;
        #pragma unroll
        for (int w = 0; w < 32; w++) tot += sd[w];
        out[0] = (float)(tot / (double)NLOSS);
    }
}

// ---------------------------------------------------------------------------
// host
// ---------------------------------------------------------------------------
extern "C" void kernel_launch(void* const* d_in, const int* in_sizes, int n_in,
                              void* d_out, int out_size)
{
    const float* feat   = (const float*)d_in[0];
    const float* reward = (const float*)d_in[1];
    const float* cont   = (const float*)d_in[2];
    const int*   act    = (const int*)  d_in[3];
    const float* pW_in  = (const float*)d_in[4];
    const float* pW_hid = (const float*)d_in[5];
    const float* p_gn   = (const float*)d_in[6];
    const float* pHw    = (const float*)d_in[7];
    const float* pHb    = (const float*)d_in[8];
    const float* vW_in  = (const float*)d_in[9];
    const float* vW_hid = (const float*)d_in[10];
    const float* v_gn   = (const float*)d_in[11];
    const float* vHw    = (const float*)d_in[12];
    const float* vHb    = (const float*)d_in[13];
    const float* sW_in  = (const float*)d_in[14];
    const float* sW_hid = (const float*)d_in[15];
    const float* s_gn   = (const float*)d_in[16];
    const float* sHw    = (const float*)d_in[17];
    const float* sHb    = (const float*)d_in[18];

    float *h0, *vslog, *plg, *smean, *ret, *wgt, *scale, *loss;
    __nv_bfloat16 *hb, *fhi, *flo, *a_hi, *a_lo, *w_hi, *w_lo;
    __nv_bfloat16 *hvs_hi, *hvs_lo, *hp_hi, *hp_lo;
    cudaGetSymbolAddress((void**)&h0, g_h0);
    cudaGetSymbolAddress((void**)&hb, g_hb);
    cudaGetSymbolAddress((void**)&fhi, g_fhi);
    cudaGetSymbolAddress((void**)&flo, g_flo);
    cudaGetSymbolAddress((void**)&a_hi, g_a_hi);
    cudaGetSymbolAddress((void**)&a_lo, g_a_lo);
    cudaGetSymbolAddress((void**)&vslog, g_vslog);
    cudaGetSymbolAddress((void**)&plg, g_plog);
    cudaGetSymbolAddress((void**)&smean, g_smean);
    cudaGetSymbolAddress((void**)&ret, g_ret);
    cudaGetSymbolAddress((void**)&wgt, g_wgt);
    cudaGetSymbolAddress((void**)&scale, g_scale);
    cudaGetSymbolAddress((void**)&loss, g_loss);
    cudaGetSymbolAddress((void**)&w_hi, g_w_hi);
    cudaGetSymbolAddress((void**)&w_lo, g_w_lo);
    cudaGetSymbolAddress((void**)&hvs_hi, g_hvs_hi);
    cudaGetSymbolAddress((void**)&hvs_lo, g_hvs_lo);
    cudaGetSymbolAddress((void**)&hp_hi, g_hp_hi);
    cudaGetSymbolAddress((void**)&hp_lo, g_hp_lo);

    float* vlog = vslog;
    float* slog = vslog + LSTR;

    cudaFuncSetAttribute(tc_gemm, cudaFuncAttributeMaxDynamicSharedMemorySize, SMEM_B);

    dim3 tb(32, 8);
    split_wt15_kernel<<<dim3(32, 32, 15), tb>>>(
        vW_in, sW_in, pW_in, vW_hid, sW_hid, pW_hid, w_hi, w_lo);
    split_act_kernel<<<NTOK, 256>>>(feat, fhi, flo);
    split_wt_kernel<<<dim3(32, 2), tb>>>(pHw, hp_hi, hp_lo, Ac);

    // 5 fused layer GEMMs (net: 0=v x1/bf16out, 1=s x3/fp32out, 2=p x1/bf16out)
    for (int l = 0; l < 5; l++) {
        const __nv_bfloat16* Ah = (l == 0) ? fhi : a_hi;
        const __nv_bfloat16* Al = (l == 0) ? flo : a_lo;
        size_t aStr = (l == 0) ? 0 : ASTR;
        tc_gemm<<<dim3(NTOK / 128, 8, 3), 128, SMEM_B>>>(
            Ah, Al, aStr,
            w_hi + (size_t)l * Uc * Uc, w_lo + (size_t)l * Uc * Uc, WSTR,
            nullptr, nullptr, h0, hb, ASTR, Uc,
            /*loMask=*/0b010, /*bfMask=*/0b101);
        rms3_kernel<<<dim3(NTOK, 3), 256>>>(
            h0, hb, v_gn + (size_t)l * Uc, s_gn + (size_t)l * Uc, p_gn + (size_t)l * Uc,
            a_hi, a_lo);
    }

    // head weight splits (needed only now)
    split_wt_kernel<<<dim3(32, 8), tb>>>(vHw, hvs_hi, hvs_lo, NBc);
    split_wt_kernel<<<dim3(32, 8), tb>>>(sHw, hvs_hi + HSTR, hvs_lo + HSTR, NBc);

    // heads: v+s fused (net 0 = v x1, net 1 = s x3), p separate (x1); fp32 out
    tc_gemm<<<dim3(NTOK / 128, 2, 2), 128, SMEM_B>>>(
        a_hi, a_lo, ASTR, hvs_hi, hvs_lo, HSTR,
        vHb, sHb, vslog, hb, LSTR, NBc, /*loMask=*/0b10, /*bfMask=*/0);
    tc_gemm<<<dim3(NTOK / 128, 1, 1), 128, SMEM_B>>>(
        a_hi + 2 * ASTR, a_lo + 2 * ASTR, 0, hp_hi, hp_lo, 0,
        pHb, nullptr, plg, hb, 0, Ac, /*loMask=*/0, /*bfMask=*/0);

    slowmean_kernel<<<NTOK, 256>>>(slog, smean);
    lamret_kernel<<<1, 64>>>(reward, cont, smean, ret, wgt);
    percentile_kernel<<<1, 1024>>>(ret, scale);
    loss_kernel<<<NLOSS, 256>>>(vlog, plg, smean, ret, wgt, act, scale, loss);
    reduce_kernel<<<1, 1024>>>(loss, (float*)d_out);
}